// round 3
// baseline (speedup 1.0000x reference)
#include <cuda_runtime.h>
#include <math.h>

// Problem constants
static constexpr int Bb  = 8;
static constexpr int Tt  = 1024;
static constexpr int Uu  = 512;
static constexpr int Hh  = 8;
static constexpr int DH  = 64;
static constexpr int HB  = 64;           // H*B
static constexpr int MR  = Bb * Tt;      // 8192 rows

// Scratch (device globals: allocation-free rule)
__device__ float g_qh[HB * Tt * DH];     // head-split q_emb [hb][t][d]
__device__ float g_kh[HB * Tt * DH];
__device__ float g_vh[HB * Tt * DH];
__device__ float g_att[MR * Uu];         // merged attention output [row][U]
__device__ float g_proj[MR * Uu];        // after out-proj + relu + residual

// ---------------------------------------------------------------------------
// Projection GEMM: C = relu(A @ W + b), A [8192,512], W [512,512]
// z = 0/1/2 -> q/k/v.  Output written head-split: dst[(h*8+b)*1024 + t][d]
// Tile 64x64, BK=16, 256 threads, 4x4 micro-tile.
// ---------------------------------------------------------------------------
__global__ __launch_bounds__(256) void proj_gemm(
    const float* __restrict__ q, const float* __restrict__ k, const float* __restrict__ v,
    const float* __restrict__ Wq, const float* __restrict__ Wk, const float* __restrict__ Wv,
    const float* __restrict__ bq, const float* __restrict__ bk, const float* __restrict__ bv)
{
    __shared__ float As[16][68];
    __shared__ float Ws[16][64];

    const int z = blockIdx.z;
    const float* A    = (z == 0) ? q  : (z == 1) ? k  : v;
    const float* W    = (z == 0) ? Wq : (z == 1) ? Wk : Wv;
    const float* bias = (z == 0) ? bq : (z == 1) ? bk : bv;
    float* dst        = (z == 0) ? g_qh : (z == 1) ? g_kh : g_vh;

    const int tid = threadIdx.x;
    const int tn = tid & 15, tm = tid >> 4;
    const int rowBase = blockIdx.y * 64;
    const int nBase   = blockIdx.x * 64;

    const int lm = tid >> 2, lkq = tid & 3;   // A loader
    const int lk = tid >> 4, lnq = tid & 15;  // W loader

    float acc[4][4] = {};

    for (int kb = 0; kb < Uu; kb += 16) {
        float4 a4 = *(const float4*)&A[(size_t)(rowBase + lm) * Uu + kb + lkq * 4];
        float4 w4 = *(const float4*)&W[(size_t)(kb + lk) * Uu + nBase + lnq * 4];
        __syncthreads();
        As[lkq * 4 + 0][lm] = a4.x;
        As[lkq * 4 + 1][lm] = a4.y;
        As[lkq * 4 + 2][lm] = a4.z;
        As[lkq * 4 + 3][lm] = a4.w;
        *(float4*)&Ws[lk][lnq * 4] = w4;
        __syncthreads();
#pragma unroll
        for (int kk = 0; kk < 16; ++kk) {
            float4 ra = *(const float4*)&As[kk][tm * 4];
            float4 rb = *(const float4*)&Ws[kk][tn * 4];
            float av[4] = {ra.x, ra.y, ra.z, ra.w};
            float bv4[4] = {rb.x, rb.y, rb.z, rb.w};
#pragma unroll
            for (int i = 0; i < 4; ++i)
#pragma unroll
                for (int j = 0; j < 4; ++j)
                    acc[i][j] = fmaf(av[i], bv4[j], acc[i][j]);
        }
    }

    const int h = blockIdx.x;  // since BN == DH == 64
    float4 bia = *(const float4*)&bias[nBase + tn * 4];
#pragma unroll
    for (int i = 0; i < 4; ++i) {
        int row = rowBase + tm * 4 + i;
        int bidx = row >> 10, t = row & 1023;
        float4 o;
        o.x = fmaxf(acc[i][0] + bia.x, 0.f);
        o.y = fmaxf(acc[i][1] + bia.y, 0.f);
        o.z = fmaxf(acc[i][2] + bia.z, 0.f);
        o.w = fmaxf(acc[i][3] + bia.w, 0.f);
        *(float4*)&dst[((size_t)(h * 8 + bidx) * Tt + t) * DH + tn * 4] = o;
    }
}

// ---------------------------------------------------------------------------
// Output projection: C = relu(A @ Wo + bo) + q,  A = g_att, write g_proj
// ---------------------------------------------------------------------------
__global__ __launch_bounds__(256) void outproj_gemm(
    const float* __restrict__ Wo, const float* __restrict__ bo,
    const float* __restrict__ qres)
{
    __shared__ float As[16][68];
    __shared__ float Ws[16][64];

    const int tid = threadIdx.x;
    const int tn = tid & 15, tm = tid >> 4;
    const int rowBase = blockIdx.y * 64;
    const int nBase   = blockIdx.x * 64;

    const int lm = tid >> 2, lkq = tid & 3;
    const int lk = tid >> 4, lnq = tid & 15;

    float acc[4][4] = {};

    for (int kb = 0; kb < Uu; kb += 16) {
        float4 a4 = *(const float4*)&g_att[(size_t)(rowBase + lm) * Uu + kb + lkq * 4];
        float4 w4 = *(const float4*)&Wo[(size_t)(kb + lk) * Uu + nBase + lnq * 4];
        __syncthreads();
        As[lkq * 4 + 0][lm] = a4.x;
        As[lkq * 4 + 1][lm] = a4.y;
        As[lkq * 4 + 2][lm] = a4.z;
        As[lkq * 4 + 3][lm] = a4.w;
        *(float4*)&Ws[lk][lnq * 4] = w4;
        __syncthreads();
#pragma unroll
        for (int kk = 0; kk < 16; ++kk) {
            float4 ra = *(const float4*)&As[kk][tm * 4];
            float4 rb = *(const float4*)&Ws[kk][tn * 4];
            float av[4] = {ra.x, ra.y, ra.z, ra.w};
            float bv4[4] = {rb.x, rb.y, rb.z, rb.w};
#pragma unroll
            for (int i = 0; i < 4; ++i)
#pragma unroll
                for (int j = 0; j < 4; ++j)
                    acc[i][j] = fmaf(av[i], bv4[j], acc[i][j]);
        }
    }

    float4 bia = *(const float4*)&bo[nBase + tn * 4];
#pragma unroll
    for (int i = 0; i < 4; ++i) {
        int row = rowBase + tm * 4 + i;
        float4 r4 = *(const float4*)&qres[(size_t)row * Uu + nBase + tn * 4];
        float4 o;
        o.x = fmaxf(acc[i][0] + bia.x, 0.f) + r4.x;
        o.y = fmaxf(acc[i][1] + bia.y, 0.f) + r4.y;
        o.z = fmaxf(acc[i][2] + bia.z, 0.f) + r4.z;
        o.w = fmaxf(acc[i][3] + bia.w, 0.f) + r4.w;
        *(float4*)&g_proj[(size_t)row * Uu + nBase + tn * 4] = o;
    }
}

// ---------------------------------------------------------------------------
// Flash attention with fused relative-position bias (rel_k) and rel_v side
// accumulation.  One block per (q-tile of 64 rows, hb).  256 threads, thread
// (tm,tn) owns S/O micro-tile rows 4tm..4tm+3, cols 4tn..4tn+3.
// ---------------------------------------------------------------------------
struct AttnSmem {
    float qT[64][68];     // q transposed [d][r], pre-scaled by 1/8
    float kT[64][68];     // k transposed [d][c]
    float v [64][68];     // v row-major [c][d]
    float pT[64][68];     // p transposed [c][r]
    float qrel[64][17];   // (q/8) . pe_k[m]
    float wsum[64][16];   // slots m=1..16 (exact near-diagonal probabilities)
    float pek[17][68];
    float pev[17][68];
};

__global__ __launch_bounds__(256) void attn_kernel(
    const float* __restrict__ pe_k, const float* __restrict__ pe_v)
{
    extern __shared__ __align__(16) char smem_raw[];
    AttnSmem& s = *reinterpret_cast<AttnSmem*>(smem_raw);

    const int tid = threadIdx.x;
    const int tn = tid & 15, tm = tid >> 4;
    const int it = blockIdx.x;   // query tile
    const int hb = blockIdx.y;   // h*8 + b
    const int h = hb >> 3, bidx = hb & 7;

    const float* qbase = g_qh + (size_t)hb * Tt * DH;
    const float* kbase = g_kh + (size_t)hb * Tt * DH;
    const float* vbase = g_vh + (size_t)hb * Tt * DH;

    // Load q tile transposed (scaled by 1/sqrt(DH) = 0.125)
    for (int i = tid; i < 64 * 16; i += 256) {
        int r = i & 63, dq = i >> 6;
        float4 a = *(const float4*)&qbase[(size_t)(it * 64 + r) * DH + dq * 4];
        s.qT[dq * 4 + 0][r] = a.x * 0.125f;
        s.qT[dq * 4 + 1][r] = a.y * 0.125f;
        s.qT[dq * 4 + 2][r] = a.z * 0.125f;
        s.qT[dq * 4 + 3][r] = a.w * 0.125f;
    }
    // Load pe_k / pe_v rows 0..16
    for (int i = tid; i < 17 * 16; i += 256) {
        int m = i / 16, dq = i % 16;
        *(float4*)&s.pek[m][dq * 4] = *(const float4*)&pe_k[m * DH + dq * 4];
        *(float4*)&s.pev[m][dq * 4] = *(const float4*)&pe_v[m * DH + dq * 4];
    }
    for (int i = tid; i < 64 * 16; i += 256)
        (&s.wsum[0][0])[i] = 0.f;
    __syncthreads();

    // qrel[r][m] = (q/8) . pe_k[m]
    for (int i = tid; i < 64 * 17; i += 256) {
        int r = i / 17, m = i % 17;
        float acc = 0.f;
#pragma unroll 16
        for (int d = 0; d < DH; ++d) acc = fmaf(s.qT[d][r], s.pek[m][d], acc);
        s.qrel[r][m] = acc;
    }

    float O[4][4] = {};
    float mrow[4] = {-1e30f, -1e30f, -1e30f, -1e30f};
    float lrow[4] = {};
    const int tglob0 = it * 64 + tm * 4;

    for (int jt = 0; jt <= it; ++jt) {
        __syncthreads();
        // Load K (transposed) and V tiles
        for (int i = tid; i < 64 * 16; i += 256) {
            int c = i & 63, dq = i >> 6;
            float4 a = *(const float4*)&kbase[(size_t)(jt * 64 + c) * DH + dq * 4];
            s.kT[dq * 4 + 0][c] = a.x;
            s.kT[dq * 4 + 1][c] = a.y;
            s.kT[dq * 4 + 2][c] = a.z;
            s.kT[dq * 4 + 3][c] = a.w;
            float4 b = *(const float4*)&vbase[(size_t)(jt * 64 + c) * DH + dq * 4];
            *(float4*)&s.v[c][dq * 4] = b;
        }
        __syncthreads();

        // S = (q/8) @ k^T
        float sc[4][4] = {};
#pragma unroll 16
        for (int d = 0; d < DH; ++d) {
            float4 a = *(const float4*)&s.qT[d][tm * 4];
            float4 b = *(const float4*)&s.kT[d][tn * 4];
            float av[4] = {a.x, a.y, a.z, a.w};
            float bv4[4] = {b.x, b.y, b.z, b.w};
#pragma unroll
            for (int i = 0; i < 4; ++i)
#pragma unroll
                for (int j = 0; j < 4; ++j)
                    sc[i][j] = fmaf(av[i], bv4[j], sc[i][j]);
        }

        // rel_k bias + causal mask
#pragma unroll
        for (int i = 0; i < 4; ++i) {
            int tg = tglob0 + i;
#pragma unroll
            for (int j = 0; j < 4; ++j) {
                int sg = jt * 64 + tn * 4 + j;
                int delta = sg - tg;
                if (delta > 0) sc[i][j] = -1e30f;
                else {
                    int mi = delta + 16; if (mi < 0) mi = 0;
                    sc[i][j] += s.qrel[tm * 4 + i][mi];
                }
            }
        }

        // row max over 16 lanes
        float mt[4];
#pragma unroll
        for (int i = 0; i < 4; ++i)
            mt[i] = fmaxf(fmaxf(sc[i][0], sc[i][1]), fmaxf(sc[i][2], sc[i][3]));
#pragma unroll
        for (int off = 1; off < 16; off <<= 1)
#pragma unroll
            for (int i = 0; i < 4; ++i)
                mt[i] = fmaxf(mt[i], __shfl_xor_sync(0xffffffffu, mt[i], off));

        float alpha[4], psum[4];
#pragma unroll
        for (int i = 0; i < 4; ++i) {
            float mnew = fmaxf(mrow[i], mt[i]);
            alpha[i] = expf(mrow[i] - mnew);
            mrow[i] = mnew;
            psum[i] = 0.f;
#pragma unroll
            for (int j = 0; j < 4; ++j) {
                sc[i][j] = expf(sc[i][j] - mnew);
                psum[i] += sc[i][j];
            }
        }
#pragma unroll
        for (int off = 1; off < 16; off <<= 1)
#pragma unroll
            for (int i = 0; i < 4; ++i)
                psum[i] += __shfl_xor_sync(0xffffffffu, psum[i], off);
#pragma unroll
        for (int i = 0; i < 4; ++i) {
            lrow[i] = lrow[i] * alpha[i] + psum[i];
#pragma unroll
            for (int j = 0; j < 4; ++j) O[i][j] *= alpha[i];
        }

        // wsum bookkeeping (row's 16 lanes are in one half-warp)
#pragma unroll
        for (int i = 0; i < 4; ++i)
            s.wsum[tm * 4 + i][tn] *= alpha[i];
        __syncwarp();
#pragma unroll
        for (int i = 0; i < 4; ++i) {
            int tg = tglob0 + i;
#pragma unroll
            for (int j = 0; j < 4; ++j) {
                int delta = (jt * 64 + tn * 4 + j) - tg;
                if (delta >= -15 && delta <= 0)
                    s.wsum[tm * 4 + i][delta + 15] += sc[i][j];
            }
        }
        __syncwarp();

        // write P transposed
#pragma unroll
        for (int j = 0; j < 4; ++j) {
            float4 p4 = make_float4(sc[0][j], sc[1][j], sc[2][j], sc[3][j]);
            *(float4*)&s.pT[tn * 4 + j][tm * 4] = p4;
        }
        __syncthreads();

        // O += P @ V
#pragma unroll 16
        for (int c = 0; c < 64; ++c) {
            float4 p = *(const float4*)&s.pT[c][tm * 4];
            float4 vv = *(const float4*)&s.v[c][tn * 4];
            float pv[4] = {p.x, p.y, p.z, p.w};
            float vr[4] = {vv.x, vv.y, vv.z, vv.w};
#pragma unroll
            for (int i = 0; i < 4; ++i)
#pragma unroll
                for (int j = 0; j < 4; ++j)
                    O[i][j] = fmaf(pv[i], vr[j], O[i][j]);
        }
    }
    __syncthreads();

    // Epilogue: add rel_v contribution, normalize, write merged layout
#pragma unroll
    for (int i = 0; i < 4; ++i) {
        int r = tm * 4 + i;
        int tg = tglob0 + i;
        float wm[16], sumw = 0.f;
#pragma unroll
        for (int m = 0; m < 16; ++m) { wm[m] = s.wsum[r][m]; sumw += wm[m]; }
        float w0 = lrow[i] - sumw;
        float inv = 1.f / lrow[i];
        float4 o;
        float* op = &o.x;
#pragma unroll
        for (int j = 0; j < 4; ++j) {
            int d = tn * 4 + j;
            float acc = O[i][j] + w0 * s.pev[0][d];
#pragma unroll
            for (int m = 1; m <= 16; ++m)
                acc = fmaf(wm[m - 1], s.pev[m][d], acc);
            op[j] = acc * inv;
        }
        *(float4*)&g_att[((size_t)(bidx * Tt) + tg) * Uu + h * DH + tn * 4] = o;
    }
}

// ---------------------------------------------------------------------------
// LayerNorm over last dim (512), eps = 1e-3.  Reads g_proj device global
// directly (passing a __device__ symbol from host code is invalid!).
// ---------------------------------------------------------------------------
__global__ __launch_bounds__(128) void ln_kernel(
    const float* __restrict__ gamma,
    const float* __restrict__ beta, float* __restrict__ out)
{
    const int row = blockIdx.x;
    const int tid = threadIdx.x;
    float4 v = *(const float4*)&g_proj[(size_t)row * Uu + tid * 4];
    float sum = v.x + v.y + v.z + v.w;
    float sq = v.x * v.x + v.y * v.y + v.z * v.z + v.w * v.w;
#pragma unroll
    for (int off = 16; off; off >>= 1) {
        sum += __shfl_xor_sync(0xffffffffu, sum, off);
        sq  += __shfl_xor_sync(0xffffffffu, sq, off);
    }
    __shared__ float red[8];
    int warp = tid >> 5, lane = tid & 31;
    if (lane == 0) { red[warp] = sum; red[4 + warp] = sq; }
    __syncthreads();
    sum = red[0] + red[1] + red[2] + red[3];
    sq  = red[4] + red[5] + red[6] + red[7];
    float mu = sum * (1.f / Uu);
    float var = sq * (1.f / Uu) - mu * mu;
    float rstd = rsqrtf(var + 1e-3f);
    float4 g = *(const float4*)&gamma[tid * 4];
    float4 be = *(const float4*)&beta[tid * 4];
    float4 o;
    o.x = (v.x - mu) * rstd * g.x + be.x;
    o.y = (v.y - mu) * rstd * g.y + be.y;
    o.z = (v.z - mu) * rstd * g.z + be.z;
    o.w = (v.w - mu) * rstd * g.w + be.w;
    *(float4*)&out[(size_t)row * Uu + tid * 4] = o;
}

// ---------------------------------------------------------------------------
// Input binding: detect permutation from in_sizes.
//   sizes: q/k/v = 4194304, W* = 262144, b*/gamma/beta = 512, pe_* = 2112
// Candidates:
//   P1 insertion : q k v Wq bq Wk bk Wv bv Wo bo gamma beta pe_k pe_v
//   P2 ASCII sort: Wk Wo Wq Wv beta bk bo bq bv gamma k pe_k pe_v q v
//   P3 lower sort: beta bk bo bq bv gamma k pe_k pe_v q v Wk Wo Wq Wv
// ---------------------------------------------------------------------------
extern "C" void kernel_launch(void* const* d_in, const int* in_sizes, int n_in,
                              void* d_out, int out_size) {
    (void)n_in; (void)out_size;

    int iq, ik, iv, iWq, ibq, iWk, ibk, iWv, ibv, iWo, ibo, ig, ibe, ipk, ipv;
    if (in_sizes[0] == Bb * Tt * Uu) {
        // P1 insertion order
        iq = 0; ik = 1; iv = 2; iWq = 3; ibq = 4; iWk = 5; ibk = 6;
        iWv = 7; ibv = 8; iWo = 9; ibo = 10; ig = 11; ibe = 12; ipk = 13; ipv = 14;
    } else if (in_sizes[0] == Uu * Uu) {
        // P2 ASCII sort (uppercase first)
        iWk = 0; iWo = 1; iWq = 2; iWv = 3; ibe = 4; ibk = 5; ibo = 6;
        ibq = 7; ibv = 8; ig = 9; ik = 10; ipk = 11; ipv = 12; iq = 13; iv = 14;
    } else {
        // P3 case-insensitive sort
        ibe = 0; ibk = 1; ibo = 2; ibq = 3; ibv = 4; ig = 5; ik = 6;
        ipk = 7; ipv = 8; iq = 9; iv = 10; iWk = 11; iWo = 12; iWq = 13; iWv = 14;
    }

    const float* q    = (const float*)d_in[iq];
    const float* k    = (const float*)d_in[ik];
    const float* v    = (const float*)d_in[iv];
    const float* Wq   = (const float*)d_in[iWq];
    const float* bq   = (const float*)d_in[ibq];
    const float* Wk   = (const float*)d_in[iWk];
    const float* bk   = (const float*)d_in[ibk];
    const float* Wv   = (const float*)d_in[iWv];
    const float* bv   = (const float*)d_in[ibv];
    const float* Wo   = (const float*)d_in[iWo];
    const float* bo   = (const float*)d_in[ibo];
    const float* gamma= (const float*)d_in[ig];
    const float* beta = (const float*)d_in[ibe];
    const float* pek  = (const float*)d_in[ipk];
    const float* pev  = (const float*)d_in[ipv];
    float* out = (float*)d_out;

    cudaFuncSetAttribute(attn_kernel, cudaFuncAttributeMaxDynamicSharedMemorySize,
                         (int)sizeof(AttnSmem));

    proj_gemm<<<dim3(8, 128, 3), 256>>>(q, k, v, Wq, Wk, Wv, bq, bk, bv);
    attn_kernel<<<dim3(16, 64), 256, sizeof(AttnSmem)>>>(pek, pev);
    outproj_gemm<<<dim3(8, 128), 256>>>(Wo, bo, q);
    ln_kernel<<<MR, 128>>>(gamma, beta, out);
}

// round 4
// speedup vs baseline: 1.4638x; 1.4638x over previous
#include <cuda_runtime.h>
#include <math.h>
#include <stdint.h>

// Problem constants
static constexpr int Bb  = 8;
static constexpr int Tt  = 1024;
static constexpr int Uu  = 512;
static constexpr int DH  = 64;
static constexpr int HB  = 64;           // H*B
static constexpr int MR  = Bb * Tt;      // 8192 rows

// Scratch (device globals: allocation-free rule)
__device__ float g_qh[HB * Tt * DH];     // head-split q_emb [hb][t][d]
__device__ float g_kh[HB * Tt * DH];
__device__ float g_vh[HB * Tt * DH];
__device__ float g_att[MR * Uu];         // merged attention output [row][U]
__device__ float g_proj[MR * Uu];        // after out-proj + relu + residual

// ---------------------------------------------------------------------------
// TF32 helpers
// ---------------------------------------------------------------------------
__device__ __forceinline__ uint32_t f2tf32(float f) {
    uint32_t u;
    asm("cvt.rna.tf32.f32 %0, %1;" : "=r"(u) : "f"(f));
    return u;
}

__device__ __forceinline__ void mma_tf32(float c[4], const uint32_t a[4], const uint32_t b[2]) {
    asm volatile(
        "mma.sync.aligned.m16n8k8.row.col.f32.tf32.tf32.f32 "
        "{%0,%1,%2,%3}, {%4,%5,%6,%7}, {%8,%9}, {%0,%1,%2,%3};"
        : "+f"(c[0]), "+f"(c[1]), "+f"(c[2]), "+f"(c[3])
        : "r"(a[0]), "r"(a[1]), "r"(a[2]), "r"(a[3]), "r"(b[0]), "r"(b[1]));
}

// ---------------------------------------------------------------------------
// TF32 GEMM: 128x128 tile, BK=16, 256 threads (8 warps as 2x4, warp tile
// 64x32).  Double-buffered smem.  MODE 0: qkv projection (head-split output,
// relu+bias).  MODE 1: out projection (relu+bias+residual, row-major output).
// ---------------------------------------------------------------------------
template <int MODE>
__global__ __launch_bounds__(256) void gemm_tf32(
    const float* __restrict__ A, const float* __restrict__ W,
    const float* __restrict__ bias, const float* __restrict__ res,
    float* __restrict__ dst)
{
    __shared__ uint32_t As[2][128][20];   // [row][k], pad to 20
    __shared__ uint32_t Bs[2][16][136];   // [k][n], pad to 136

    const int tid  = threadIdx.x;
    const int lane = tid & 31;
    const int wid  = tid >> 5;
    const int wm   = wid >> 2;            // 0..1
    const int wn   = wid & 3;             // 0..3
    const int rowBase = blockIdx.y * 128;
    const int nBase   = blockIdx.x * 128;

    // loaders
    const int ar  = tid >> 2;             // 0..63  (rows ar, ar+64)
    const int ac4 = tid & 3;              // k-float4 0..3
    const int br  = tid >> 5;             // 0..7   (rows br, br+8)
    const int bc4 = tid & 31;             // n-float4 0..31

    float4 pa[2], pb[2];

    auto ldg = [&](int kb) {
        pa[0] = *(const float4*)&A[(size_t)(rowBase + ar) * Uu + kb + ac4 * 4];
        pa[1] = *(const float4*)&A[(size_t)(rowBase + ar + 64) * Uu + kb + ac4 * 4];
        pb[0] = *(const float4*)&W[(size_t)(kb + br) * Uu + nBase + bc4 * 4];
        pb[1] = *(const float4*)&W[(size_t)(kb + br + 8) * Uu + nBase + bc4 * 4];
    };
    auto sts = [&](int buf) {
#pragma unroll
        for (int i = 0; i < 2; ++i) {
            const float* p = &pa[i].x;
#pragma unroll
            for (int j = 0; j < 4; ++j)
                As[buf][ar + i * 64][ac4 * 4 + j] = f2tf32(p[j]);
            const float* q = &pb[i].x;
#pragma unroll
            for (int j = 0; j < 4; ++j)
                Bs[buf][br + i * 8][bc4 * 4 + j] = f2tf32(q[j]);
        }
    };

    float c[4][4][4] = {};   // [mt][nt][4]

    ldg(0);
    sts(0);
    __syncthreads();

    const int r0 = wm * 64 + (lane >> 2);
    const int n0 = wn * 32 + (lane >> 2);
    const int kq = lane & 3;

    for (int kb = 0; kb < Uu / 16; ++kb) {
        const int cur = kb & 1;
        if (kb + 1 < Uu / 16) ldg((kb + 1) * 16);

#pragma unroll
        for (int ks = 0; ks < 2; ++ks) {
            const int k0 = ks * 8 + kq;
            uint32_t a[4][4];
#pragma unroll
            for (int mt = 0; mt < 4; ++mt) {
                a[mt][0] = As[cur][r0 + mt * 16][k0];
                a[mt][1] = As[cur][r0 + mt * 16 + 8][k0];
                a[mt][2] = As[cur][r0 + mt * 16][k0 + 4];
                a[mt][3] = As[cur][r0 + mt * 16 + 8][k0 + 4];
            }
            uint32_t b[4][2];
#pragma unroll
            for (int nt = 0; nt < 4; ++nt) {
                b[nt][0] = Bs[cur][k0][n0 + nt * 8];
                b[nt][1] = Bs[cur][k0 + 4][n0 + nt * 8];
            }
#pragma unroll
            for (int mt = 0; mt < 4; ++mt)
#pragma unroll
                for (int nt = 0; nt < 4; ++nt)
                    mma_tf32(c[mt][nt], a[mt], b[nt]);
        }

        if (kb + 1 < Uu / 16) sts(cur ^ 1);
        __syncthreads();
    }

    // Epilogue
#pragma unroll
    for (int mt = 0; mt < 4; ++mt) {
        const int rbase = rowBase + wm * 64 + mt * 16 + (lane >> 2);
#pragma unroll
        for (int nt = 0; nt < 4; ++nt) {
            const int n = nBase + wn * 32 + nt * 8 + (lane & 3) * 2;
            const float2 bi = *(const float2*)&bias[n];
#pragma unroll
            for (int half = 0; half < 2; ++half) {
                const int m = rbase + half * 8;
                float2 o;
                o.x = fmaxf(c[mt][nt][half * 2 + 0] + bi.x, 0.f);
                o.y = fmaxf(c[mt][nt][half * 2 + 1] + bi.y, 0.f);
                if (MODE == 0) {
                    // head-split: dst[(h*8 + b)*1024 + t][d]
                    const int h = n >> 6, d = n & 63;
                    const int bidx = m >> 10, t = m & 1023;
                    *(float2*)&dst[((size_t)(h * 8 + bidx) * Tt + t) * DH + d] = o;
                } else {
                    const float2 r2 = *(const float2*)&res[(size_t)m * Uu + n];
                    o.x += r2.x;
                    o.y += r2.y;
                    *(float2*)&dst[(size_t)m * Uu + n] = o;
                }
            }
        }
    }
}

// ---------------------------------------------------------------------------
// Flash attention with fused relative-position bias (rel_k) and rel_v side
// accumulation.  One block per (q-tile of 64 rows, hb).  256 threads, thread
// (tm,tn) owns S/O micro-tile rows 4tm..4tm+3, cols 4tn..4tn+3.
// ---------------------------------------------------------------------------
struct AttnSmem {
    float qT[64][68];     // q transposed [d][r], pre-scaled by 1/8
    float kT[64][68];     // k transposed [d][c]
    float v [64][68];     // v row-major [c][d]
    float pT[64][68];     // p transposed [c][r]
    float qrel[64][17];   // (q/8) . pe_k[m]
    float wsum[64][16];   // slots m=1..16 (exact near-diagonal probabilities)
    float pek[17][68];
    float pev[17][68];
};

__global__ __launch_bounds__(256) void attn_kernel(
    const float* __restrict__ pe_k, const float* __restrict__ pe_v)
{
    extern __shared__ __align__(16) char smem_raw[];
    AttnSmem& s = *reinterpret_cast<AttnSmem*>(smem_raw);

    const int tid = threadIdx.x;
    const int tn = tid & 15, tm = tid >> 4;
    const int it = blockIdx.x;   // query tile
    const int hb = blockIdx.y;   // h*8 + b
    const int h = hb >> 3, bidx = hb & 7;

    const float* qbase = g_qh + (size_t)hb * Tt * DH;
    const float* kbase = g_kh + (size_t)hb * Tt * DH;
    const float* vbase = g_vh + (size_t)hb * Tt * DH;

    // Load q tile transposed (scaled by 1/sqrt(DH) = 0.125)
    for (int i = tid; i < 64 * 16; i += 256) {
        int r = i & 63, dq = i >> 6;
        float4 a = *(const float4*)&qbase[(size_t)(it * 64 + r) * DH + dq * 4];
        s.qT[dq * 4 + 0][r] = a.x * 0.125f;
        s.qT[dq * 4 + 1][r] = a.y * 0.125f;
        s.qT[dq * 4 + 2][r] = a.z * 0.125f;
        s.qT[dq * 4 + 3][r] = a.w * 0.125f;
    }
    // Load pe_k / pe_v rows 0..16
    for (int i = tid; i < 17 * 16; i += 256) {
        int m = i / 16, dq = i % 16;
        *(float4*)&s.pek[m][dq * 4] = *(const float4*)&pe_k[m * DH + dq * 4];
        *(float4*)&s.pev[m][dq * 4] = *(const float4*)&pe_v[m * DH + dq * 4];
    }
    for (int i = tid; i < 64 * 16; i += 256)
        (&s.wsum[0][0])[i] = 0.f;
    __syncthreads();

    // qrel[r][m] = (q/8) . pe_k[m]
    for (int i = tid; i < 64 * 17; i += 256) {
        int r = i / 17, m = i % 17;
        float acc = 0.f;
#pragma unroll 16
        for (int d = 0; d < DH; ++d) acc = fmaf(s.qT[d][r], s.pek[m][d], acc);
        s.qrel[r][m] = acc;
    }

    float O[4][4] = {};
    float mrow[4] = {-1e30f, -1e30f, -1e30f, -1e30f};
    float lrow[4] = {};
    const int tglob0 = it * 64 + tm * 4;

    for (int jt = 0; jt <= it; ++jt) {
        __syncthreads();
        // Load K (transposed) and V tiles
        for (int i = tid; i < 64 * 16; i += 256) {
            int c = i & 63, dq = i >> 6;
            float4 a = *(const float4*)&kbase[(size_t)(jt * 64 + c) * DH + dq * 4];
            s.kT[dq * 4 + 0][c] = a.x;
            s.kT[dq * 4 + 1][c] = a.y;
            s.kT[dq * 4 + 2][c] = a.z;
            s.kT[dq * 4 + 3][c] = a.w;
            float4 b = *(const float4*)&vbase[(size_t)(jt * 64 + c) * DH + dq * 4];
            *(float4*)&s.v[c][dq * 4] = b;
        }
        __syncthreads();

        // S = (q/8) @ k^T
        float sc[4][4] = {};
#pragma unroll 16
        for (int d = 0; d < DH; ++d) {
            float4 a = *(const float4*)&s.qT[d][tm * 4];
            float4 b = *(const float4*)&s.kT[d][tn * 4];
            float av[4] = {a.x, a.y, a.z, a.w};
            float bv4[4] = {b.x, b.y, b.z, b.w};
#pragma unroll
            for (int i = 0; i < 4; ++i)
#pragma unroll
                for (int j = 0; j < 4; ++j)
                    sc[i][j] = fmaf(av[i], bv4[j], sc[i][j]);
        }

        // rel_k bias + causal mask
#pragma unroll
        for (int i = 0; i < 4; ++i) {
            int tg = tglob0 + i;
#pragma unroll
            for (int j = 0; j < 4; ++j) {
                int sg = jt * 64 + tn * 4 + j;
                int delta = sg - tg;
                if (delta > 0) sc[i][j] = -1e30f;
                else {
                    int mi = delta + 16; if (mi < 0) mi = 0;
                    sc[i][j] += s.qrel[tm * 4 + i][mi];
                }
            }
        }

        // row max over 16 lanes
        float mt[4];
#pragma unroll
        for (int i = 0; i < 4; ++i)
            mt[i] = fmaxf(fmaxf(sc[i][0], sc[i][1]), fmaxf(sc[i][2], sc[i][3]));
#pragma unroll
        for (int off = 1; off < 16; off <<= 1)
#pragma unroll
            for (int i = 0; i < 4; ++i)
                mt[i] = fmaxf(mt[i], __shfl_xor_sync(0xffffffffu, mt[i], off));

        float alpha[4], psum[4];
#pragma unroll
        for (int i = 0; i < 4; ++i) {
            float mnew = fmaxf(mrow[i], mt[i]);
            alpha[i] = expf(mrow[i] - mnew);
            mrow[i] = mnew;
            psum[i] = 0.f;
#pragma unroll
            for (int j = 0; j < 4; ++j) {
                sc[i][j] = expf(sc[i][j] - mnew);
                psum[i] += sc[i][j];
            }
        }
#pragma unroll
        for (int off = 1; off < 16; off <<= 1)
#pragma unroll
            for (int i = 0; i < 4; ++i)
                psum[i] += __shfl_xor_sync(0xffffffffu, psum[i], off);
#pragma unroll
        for (int i = 0; i < 4; ++i) {
            lrow[i] = lrow[i] * alpha[i] + psum[i];
#pragma unroll
            for (int j = 0; j < 4; ++j) O[i][j] *= alpha[i];
        }

        // wsum bookkeeping (row's 16 lanes are in one half-warp)
#pragma unroll
        for (int i = 0; i < 4; ++i)
            s.wsum[tm * 4 + i][tn] *= alpha[i];
        __syncwarp();
#pragma unroll
        for (int i = 0; i < 4; ++i) {
            int tg = tglob0 + i;
#pragma unroll
            for (int j = 0; j < 4; ++j) {
                int delta = (jt * 64 + tn * 4 + j) - tg;
                if (delta >= -15 && delta <= 0)
                    s.wsum[tm * 4 + i][delta + 15] += sc[i][j];
            }
        }
        __syncwarp();

        // write P transposed
#pragma unroll
        for (int j = 0; j < 4; ++j) {
            float4 p4 = make_float4(sc[0][j], sc[1][j], sc[2][j], sc[3][j]);
            *(float4*)&s.pT[tn * 4 + j][tm * 4] = p4;
        }
        __syncthreads();

        // O += P @ V
#pragma unroll 16
        for (int c = 0; c < 64; ++c) {
            float4 p = *(const float4*)&s.pT[c][tm * 4];
            float4 vv = *(const float4*)&s.v[c][tn * 4];
            float pv[4] = {p.x, p.y, p.z, p.w};
            float vr[4] = {vv.x, vv.y, vv.z, vv.w};
#pragma unroll
            for (int i = 0; i < 4; ++i)
#pragma unroll
                for (int j = 0; j < 4; ++j)
                    O[i][j] = fmaf(pv[i], vr[j], O[i][j]);
        }
    }
    __syncthreads();

    // Epilogue: add rel_v contribution, normalize, write merged layout
#pragma unroll
    for (int i = 0; i < 4; ++i) {
        int r = tm * 4 + i;
        int tg = tglob0 + i;
        float wm[16], sumw = 0.f;
#pragma unroll
        for (int m = 0; m < 16; ++m) { wm[m] = s.wsum[r][m]; sumw += wm[m]; }
        float w0 = lrow[i] - sumw;
        float inv = 1.f / lrow[i];
        float4 o;
        float* op = &o.x;
#pragma unroll
        for (int j = 0; j < 4; ++j) {
            int d = tn * 4 + j;
            float acc = O[i][j] + w0 * s.pev[0][d];
#pragma unroll
            for (int m = 1; m <= 16; ++m)
                acc = fmaf(wm[m - 1], s.pev[m][d], acc);
            op[j] = acc * inv;
        }
        *(float4*)&g_att[((size_t)(bidx * Tt) + tg) * Uu + h * DH + tn * 4] = o;
    }
}

// ---------------------------------------------------------------------------
// LayerNorm over last dim (512), eps = 1e-3.  Reads g_proj device global
// directly.
// ---------------------------------------------------------------------------
__global__ __launch_bounds__(128) void ln_kernel(
    const float* __restrict__ gamma,
    const float* __restrict__ beta, float* __restrict__ out)
{
    const int row = blockIdx.x;
    const int tid = threadIdx.x;
    float4 v = *(const float4*)&g_proj[(size_t)row * Uu + tid * 4];
    float sum = v.x + v.y + v.z + v.w;
    float sq = v.x * v.x + v.y * v.y + v.z * v.z + v.w * v.w;
#pragma unroll
    for (int off = 16; off; off >>= 1) {
        sum += __shfl_xor_sync(0xffffffffu, sum, off);
        sq  += __shfl_xor_sync(0xffffffffu, sq, off);
    }
    __shared__ float red[8];
    int warp = tid >> 5, lane = tid & 31;
    if (lane == 0) { red[warp] = sum; red[4 + warp] = sq; }
    __syncthreads();
    sum = red[0] + red[1] + red[2] + red[3];
    sq  = red[4] + red[5] + red[6] + red[7];
    float mu = sum * (1.f / Uu);
    float var = sq * (1.f / Uu) - mu * mu;
    float rstd = rsqrtf(var + 1e-3f);
    float4 g = *(const float4*)&gamma[tid * 4];
    float4 be = *(const float4*)&beta[tid * 4];
    float4 o;
    o.x = (v.x - mu) * rstd * g.x + be.x;
    o.y = (v.y - mu) * rstd * g.y + be.y;
    o.z = (v.z - mu) * rstd * g.z + be.z;
    o.w = (v.w - mu) * rstd * g.w + be.w;
    *(float4*)&out[(size_t)row * Uu + tid * 4] = o;
}

// ---------------------------------------------------------------------------
// Input binding: detect permutation from in_sizes (sizes distinguish order).
// ---------------------------------------------------------------------------
extern "C" void kernel_launch(void* const* d_in, const int* in_sizes, int n_in,
                              void* d_out, int out_size) {
    (void)n_in; (void)out_size;

    int iq, ik, iv, iWq, ibq, iWk, ibk, iWv, ibv, iWo, ibo, ig, ibe, ipk, ipv;
    if (in_sizes[0] == Bb * Tt * Uu) {
        // insertion order
        iq = 0; ik = 1; iv = 2; iWq = 3; ibq = 4; iWk = 5; ibk = 6;
        iWv = 7; ibv = 8; iWo = 9; ibo = 10; ig = 11; ibe = 12; ipk = 13; ipv = 14;
    } else if (in_sizes[0] == Uu * Uu) {
        // ASCII sort (uppercase first)
        iWk = 0; iWo = 1; iWq = 2; iWv = 3; ibe = 4; ibk = 5; ibo = 6;
        ibq = 7; ibv = 8; ig = 9; ik = 10; ipk = 11; ipv = 12; iq = 13; iv = 14;
    } else {
        // case-insensitive sort
        ibe = 0; ibk = 1; ibo = 2; ibq = 3; ibv = 4; ig = 5; ik = 6;
        ipk = 7; ipv = 8; iq = 9; iv = 10; iWk = 11; iWo = 12; iWq = 13; iWv = 14;
    }

    const float* q    = (const float*)d_in[iq];
    const float* k    = (const float*)d_in[ik];
    const float* v    = (const float*)d_in[iv];
    const float* Wq   = (const float*)d_in[iWq];
    const float* bq   = (const float*)d_in[ibq];
    const float* Wk   = (const float*)d_in[iWk];
    const float* bk   = (const float*)d_in[ibk];
    const float* Wv   = (const float*)d_in[iWv];
    const float* bv   = (const float*)d_in[ibv];
    const float* Wo   = (const float*)d_in[iWo];
    const float* bo   = (const float*)d_in[ibo];
    const float* gamma= (const float*)d_in[ig];
    const float* beta = (const float*)d_in[ibe];
    const float* pek  = (const float*)d_in[ipk];
    const float* pev  = (const float*)d_in[ipv];
    float* out = (float*)d_out;

    cudaFuncSetAttribute(attn_kernel, cudaFuncAttributeMaxDynamicSharedMemorySize,
                         (int)sizeof(AttnSmem));

    float* g_qh_p;  cudaGetSymbolAddress((void**)&g_qh_p,  g_qh);
    float* g_kh_p;  cudaGetSymbolAddress((void**)&g_kh_p,  g_kh);
    float* g_vh_p;  cudaGetSymbolAddress((void**)&g_vh_p,  g_vh);
    float* g_att_p; cudaGetSymbolAddress((void**)&g_att_p, g_att);
    float* g_proj_p;cudaGetSymbolAddress((void**)&g_proj_p,g_proj);

    // Q/K/V projections (TF32 tensor cores), head-split output
    gemm_tf32<0><<<dim3(4, 64), 256>>>(q, Wq, bq, nullptr, g_qh_p);
    gemm_tf32<0><<<dim3(4, 64), 256>>>(k, Wk, bk, nullptr, g_kh_p);
    gemm_tf32<0><<<dim3(4, 64), 256>>>(v, Wv, bv, nullptr, g_vh_p);

    attn_kernel<<<dim3(16, 64), 256, sizeof(AttnSmem)>>>(pek, pev);

    // Output projection + relu + residual (TF32)
    gemm_tf32<1><<<dim3(4, 64), 256>>>(g_att_p, Wo, bo, q, g_proj_p);

    ln_kernel<<<MR, 128>>>(gamma, beta, out);
}

// round 5
// speedup vs baseline: 2.4160x; 1.6506x over previous
#include <cuda_runtime.h>
#include <math.h>
#include <stdint.h>

// Problem constants
static constexpr int Bb  = 8;
static constexpr int Tt  = 1024;
static constexpr int Uu  = 512;
static constexpr int DH  = 64;
static constexpr int HB  = 64;           // H*B
static constexpr int MR  = Bb * Tt;      // 8192 rows

// Scratch (device globals: allocation-free rule)
__device__ float g_qh[HB * Tt * DH];     // head-split q_emb [hb][t][d]
__device__ float g_kh[HB * Tt * DH];
__device__ float g_vh[HB * Tt * DH];
__device__ float g_att[MR * Uu];         // merged attention output [row][U]
__device__ float g_proj[MR * Uu];        // after out-proj + relu + residual

// ---------------------------------------------------------------------------
// TF32 helpers
// ---------------------------------------------------------------------------
__device__ __forceinline__ uint32_t f2tf32(float f) {
    uint32_t u;
    asm("cvt.rna.tf32.f32 %0, %1;" : "=r"(u) : "f"(f));
    return u;
}

__device__ __forceinline__ void mma_tf32(float c[4], const uint32_t a[4], const uint32_t b[2]) {
    asm volatile(
        "mma.sync.aligned.m16n8k8.row.col.f32.tf32.tf32.f32 "
        "{%0,%1,%2,%3}, {%4,%5,%6,%7}, {%8,%9}, {%0,%1,%2,%3};"
        : "+f"(c[0]), "+f"(c[1]), "+f"(c[2]), "+f"(c[3])
        : "r"(a[0]), "r"(a[1]), "r"(a[2]), "r"(a[3]), "r"(b[0]), "r"(b[1]));
}

// ---------------------------------------------------------------------------
// TF32 GEMM: 128x128 tile, BK=16, 256 threads (8 warps as 2x4, warp tile
// 64x32).  Double-buffered smem.  MODE 0: qkv projection (head-split output,
// relu+bias).  MODE 1: out projection (relu+bias+residual, row-major output).
// ---------------------------------------------------------------------------
template <int MODE>
__global__ __launch_bounds__(256) void gemm_tf32(
    const float* __restrict__ A, const float* __restrict__ W,
    const float* __restrict__ bias, const float* __restrict__ res,
    float* __restrict__ dst)
{
    __shared__ uint32_t As[2][128][20];   // [row][k], pad to 20
    __shared__ uint32_t Bs[2][16][136];   // [k][n], pad to 136

    const int tid  = threadIdx.x;
    const int lane = tid & 31;
    const int wid  = tid >> 5;
    const int wm   = wid >> 2;            // 0..1
    const int wn   = wid & 3;             // 0..3
    const int rowBase = blockIdx.y * 128;
    const int nBase   = blockIdx.x * 128;

    // loaders
    const int ar  = tid >> 2;             // 0..63  (rows ar, ar+64)
    const int ac4 = tid & 3;              // k-float4 0..3
    const int br  = tid >> 5;             // 0..7   (rows br, br+8)
    const int bc4 = tid & 31;             // n-float4 0..31

    float4 pa[2], pb[2];

    auto ldg = [&](int kb) {
        pa[0] = *(const float4*)&A[(size_t)(rowBase + ar) * Uu + kb + ac4 * 4];
        pa[1] = *(const float4*)&A[(size_t)(rowBase + ar + 64) * Uu + kb + ac4 * 4];
        pb[0] = *(const float4*)&W[(size_t)(kb + br) * Uu + nBase + bc4 * 4];
        pb[1] = *(const float4*)&W[(size_t)(kb + br + 8) * Uu + nBase + bc4 * 4];
    };
    auto sts = [&](int buf) {
#pragma unroll
        for (int i = 0; i < 2; ++i) {
            const float* p = &pa[i].x;
#pragma unroll
            for (int j = 0; j < 4; ++j)
                As[buf][ar + i * 64][ac4 * 4 + j] = f2tf32(p[j]);
            const float* q = &pb[i].x;
#pragma unroll
            for (int j = 0; j < 4; ++j)
                Bs[buf][br + i * 8][bc4 * 4 + j] = f2tf32(q[j]);
        }
    };

    float c[4][4][4] = {};   // [mt][nt][4]

    ldg(0);
    sts(0);
    __syncthreads();

    const int r0 = wm * 64 + (lane >> 2);
    const int n0 = wn * 32 + (lane >> 2);
    const int kq = lane & 3;

    for (int kb = 0; kb < Uu / 16; ++kb) {
        const int cur = kb & 1;
        if (kb + 1 < Uu / 16) ldg((kb + 1) * 16);

#pragma unroll
        for (int ks = 0; ks < 2; ++ks) {
            const int k0 = ks * 8 + kq;
            uint32_t a[4][4];
#pragma unroll
            for (int mt = 0; mt < 4; ++mt) {
                a[mt][0] = As[cur][r0 + mt * 16][k0];
                a[mt][1] = As[cur][r0 + mt * 16 + 8][k0];
                a[mt][2] = As[cur][r0 + mt * 16][k0 + 4];
                a[mt][3] = As[cur][r0 + mt * 16 + 8][k0 + 4];
            }
            uint32_t b[4][2];
#pragma unroll
            for (int nt = 0; nt < 4; ++nt) {
                b[nt][0] = Bs[cur][k0][n0 + nt * 8];
                b[nt][1] = Bs[cur][k0 + 4][n0 + nt * 8];
            }
#pragma unroll
            for (int mt = 0; mt < 4; ++mt)
#pragma unroll
                for (int nt = 0; nt < 4; ++nt)
                    mma_tf32(c[mt][nt], a[mt], b[nt]);
        }

        if (kb + 1 < Uu / 16) sts(cur ^ 1);
        __syncthreads();
    }

    // Epilogue
#pragma unroll
    for (int mt = 0; mt < 4; ++mt) {
        const int rbase = rowBase + wm * 64 + mt * 16 + (lane >> 2);
#pragma unroll
        for (int nt = 0; nt < 4; ++nt) {
            const int n = nBase + wn * 32 + nt * 8 + (lane & 3) * 2;
            const float2 bi = *(const float2*)&bias[n];
#pragma unroll
            for (int half = 0; half < 2; ++half) {
                const int m = rbase + half * 8;
                float2 o;
                o.x = fmaxf(c[mt][nt][half * 2 + 0] + bi.x, 0.f);
                o.y = fmaxf(c[mt][nt][half * 2 + 1] + bi.y, 0.f);
                if (MODE == 0) {
                    // head-split: dst[(h*8 + b)*1024 + t][d]
                    const int h = n >> 6, d = n & 63;
                    const int bidx = m >> 10, t = m & 1023;
                    *(float2*)&dst[((size_t)(h * 8 + bidx) * Tt + t) * DH + d] = o;
                } else {
                    const float2 r2 = *(const float2*)&res[(size_t)m * Uu + n];
                    o.x += r2.x;
                    o.y += r2.y;
                    *(float2*)&dst[(size_t)m * Uu + n] = o;
                }
            }
        }
    }
}

// ---------------------------------------------------------------------------
// Tensor-core flash attention (TF32 mma).  One block per (q-tile 64, hb).
// 128 threads = 4 warps; warp w owns S/O rows 16w..16w+15 (full 64 cols).
// Fragment layouts identical to the validated gemm_tf32 kernel.
// Q/P strides 68, K/V strides 72 -> conflict-free fragment LDS.
// rel_k bias via qrel (17-wide per-row GEMV); rel_v via wsum slots.
// ---------------------------------------------------------------------------
struct AttnSmem {
    uint32_t Q[64][68];   // tf32 bits, pre-scaled by 0.125
    uint32_t K[64][72];   // tf32 bits
    uint32_t V[64][72];   // tf32 bits
    uint32_t P[64][68];   // tf32 bits
    float qrel[64][17];
    float wsum[64][16];
    float pek[17][68];
    float pev[17][68];
};

__global__ __launch_bounds__(128) void attn_kernel(
    const float* __restrict__ pe_k, const float* __restrict__ pe_v)
{
    extern __shared__ __align__(16) char smem_raw[];
    AttnSmem& s = *reinterpret_cast<AttnSmem*>(smem_raw);

    const int tid  = threadIdx.x;
    const int lane = tid & 31;
    const int w    = tid >> 5;
    const int kq   = lane & 3;      // fragment k / col quad
    const int ng   = lane >> 2;     // fragment group id
    const int it   = 15 - (int)blockIdx.x;   // heavy tiles first
    const int hb   = blockIdx.y;
    const int h = hb >> 3, bidx = hb & 7;

    const float* qbase = g_qh + (size_t)hb * Tt * DH;
    const float* kbase = g_kh + (size_t)hb * Tt * DH;
    const float* vbase = g_vh + (size_t)hb * Tt * DH;

    // Load Q tile (scaled by 1/8, converted to tf32)
    for (int i = tid; i < 1024; i += 128) {
        int r = i >> 4, dq = i & 15;
        float4 a = *(const float4*)&qbase[(size_t)(it * 64 + r) * DH + dq * 4];
        s.Q[r][dq * 4 + 0] = f2tf32(a.x * 0.125f);
        s.Q[r][dq * 4 + 1] = f2tf32(a.y * 0.125f);
        s.Q[r][dq * 4 + 2] = f2tf32(a.z * 0.125f);
        s.Q[r][dq * 4 + 3] = f2tf32(a.w * 0.125f);
    }
    // pe_k / pe_v rows 0..16 (fp32)
    for (int i = tid; i < 17 * 16; i += 128) {
        int m = i / 16, dq = i % 16;
        *(float4*)&s.pek[m][dq * 4] = *(const float4*)&pe_k[m * DH + dq * 4];
        *(float4*)&s.pev[m][dq * 4] = *(const float4*)&pe_v[m * DH + dq * 4];
    }
    for (int i = tid; i < 1024; i += 128)
        (&s.wsum[0][0])[i] = 0.f;
    __syncthreads();

    // qrel[r][m] = (q/8) . pe_k[m]  (Q already tf32-rounded; fine for bias)
    for (int i = tid; i < 64 * 17; i += 128) {
        int r = i / 17, m = i % 17;
        float acc = 0.f;
#pragma unroll 16
        for (int d = 0; d < DH; ++d)
            acc = fmaf(__uint_as_float(s.Q[r][d]), s.pek[m][d], acc);
        s.qrel[r][m] = acc;
    }
    __syncthreads();

    const int rl0 = w * 16 + ng;          // local row (first half)
    const float qrel0_0 = s.qrel[rl0][0];
    const float qrel0_1 = s.qrel[rl0 + 8][0];

    float o[8][4] = {};
    float mrow[2] = {-1e30f, -1e30f};
    float lrow[2] = {};

    for (int jt = 0; jt <= it; ++jt) {
        __syncthreads();
        for (int i = tid; i < 1024; i += 128) {
            int c = i >> 4, dq = i & 15;
            float4 a = *(const float4*)&kbase[(size_t)(jt * 64 + c) * DH + dq * 4];
            s.K[c][dq * 4 + 0] = f2tf32(a.x);
            s.K[c][dq * 4 + 1] = f2tf32(a.y);
            s.K[c][dq * 4 + 2] = f2tf32(a.z);
            s.K[c][dq * 4 + 3] = f2tf32(a.w);
            float4 b = *(const float4*)&vbase[(size_t)(jt * 64 + c) * DH + dq * 4];
            s.V[c][dq * 4 + 0] = f2tf32(b.x);
            s.V[c][dq * 4 + 1] = f2tf32(b.y);
            s.V[c][dq * 4 + 2] = f2tf32(b.z);
            s.V[c][dq * 4 + 3] = f2tf32(b.w);
        }
        __syncthreads();

        // ---- S = (Q/8) @ K^T via mma ----
        float sc[8][4] = {};
#pragma unroll
        for (int ks = 0; ks < 8; ++ks) {
            const int k0 = ks * 8 + kq;
            uint32_t a[4];
            a[0] = s.Q[rl0][k0];
            a[1] = s.Q[rl0 + 8][k0];
            a[2] = s.Q[rl0][k0 + 4];
            a[3] = s.Q[rl0 + 8][k0 + 4];
#pragma unroll
            for (int nt = 0; nt < 8; ++nt) {
                uint32_t b[2];
                b[0] = s.K[nt * 8 + ng][k0];
                b[1] = s.K[nt * 8 + ng][k0 + 4];
                mma_tf32(sc[nt], a, b);
            }
        }

        // ---- rel_k bias (+ causal mask on near tiles) ----
        const bool near = (jt >= it - 1);
        if (near) {
#pragma unroll
            for (int nt = 0; nt < 8; ++nt) {
#pragma unroll
                for (int ci = 0; ci < 4; ++ci) {
                    const int row_l = rl0 + ((ci >> 1) << 3);
                    const int tg = it * 64 + row_l;
                    const int sg = jt * 64 + nt * 8 + 2 * kq + (ci & 1);
                    const int delta = sg - tg;
                    if (delta > 0) sc[nt][ci] = -1e30f;
                    else {
                        int mi = delta + 16; if (mi < 0) mi = 0;
                        sc[nt][ci] += s.qrel[row_l][mi];
                    }
                }
            }
        } else {
#pragma unroll
            for (int nt = 0; nt < 8; ++nt) {
                sc[nt][0] += qrel0_0;
                sc[nt][1] += qrel0_0;
                sc[nt][2] += qrel0_1;
                sc[nt][3] += qrel0_1;
            }
        }

        // ---- online softmax ----
        float mt0 = -1e30f, mt1 = -1e30f;
#pragma unroll
        for (int nt = 0; nt < 8; ++nt) {
            mt0 = fmaxf(mt0, fmaxf(sc[nt][0], sc[nt][1]));
            mt1 = fmaxf(mt1, fmaxf(sc[nt][2], sc[nt][3]));
        }
        mt0 = fmaxf(mt0, __shfl_xor_sync(0xffffffffu, mt0, 1));
        mt0 = fmaxf(mt0, __shfl_xor_sync(0xffffffffu, mt0, 2));
        mt1 = fmaxf(mt1, __shfl_xor_sync(0xffffffffu, mt1, 1));
        mt1 = fmaxf(mt1, __shfl_xor_sync(0xffffffffu, mt1, 2));

        const float mnew0 = fmaxf(mrow[0], mt0);
        const float mnew1 = fmaxf(mrow[1], mt1);
        const float alpha0 = __expf(mrow[0] - mnew0);
        const float alpha1 = __expf(mrow[1] - mnew1);
        mrow[0] = mnew0; mrow[1] = mnew1;

        float ps0 = 0.f, ps1 = 0.f;
#pragma unroll
        for (int nt = 0; nt < 8; ++nt) {
            sc[nt][0] = __expf(sc[nt][0] - mnew0);
            sc[nt][1] = __expf(sc[nt][1] - mnew0);
            sc[nt][2] = __expf(sc[nt][2] - mnew1);
            sc[nt][3] = __expf(sc[nt][3] - mnew1);
            ps0 += sc[nt][0] + sc[nt][1];
            ps1 += sc[nt][2] + sc[nt][3];
        }
        ps0 += __shfl_xor_sync(0xffffffffu, ps0, 1);
        ps0 += __shfl_xor_sync(0xffffffffu, ps0, 2);
        ps1 += __shfl_xor_sync(0xffffffffu, ps1, 1);
        ps1 += __shfl_xor_sync(0xffffffffu, ps1, 2);
        lrow[0] = lrow[0] * alpha0 + ps0;
        lrow[1] = lrow[1] * alpha1 + ps1;

#pragma unroll
        for (int nt = 0; nt < 8; ++nt) {
            o[nt][0] *= alpha0; o[nt][1] *= alpha0;
            o[nt][2] *= alpha1; o[nt][3] *= alpha1;
        }

        // ---- wsum bookkeeping (warp-private rows) ----
#pragma unroll
        for (int j = 0; j < 4; ++j) {
            s.wsum[rl0][kq * 4 + j]     *= alpha0;
            s.wsum[rl0 + 8][kq * 4 + j] *= alpha1;
        }
        __syncwarp();
        if (near) {
#pragma unroll
            for (int nt = 0; nt < 8; ++nt) {
#pragma unroll
                for (int ci = 0; ci < 4; ++ci) {
                    const int row_l = rl0 + ((ci >> 1) << 3);
                    const int delta = (jt * 64 + nt * 8 + 2 * kq + (ci & 1)) - (it * 64 + row_l);
                    if (delta >= -15 && delta <= 0)
                        s.wsum[row_l][delta + 15] += sc[nt][ci];
                }
            }
        }
        __syncwarp();

        // ---- P -> smem (tf32), warp-private rows ----
#pragma unroll
        for (int nt = 0; nt < 8; ++nt) {
            const int c0 = nt * 8 + 2 * kq;
            s.P[rl0][c0]         = f2tf32(sc[nt][0]);
            s.P[rl0][c0 + 1]     = f2tf32(sc[nt][1]);
            s.P[rl0 + 8][c0]     = f2tf32(sc[nt][2]);
            s.P[rl0 + 8][c0 + 1] = f2tf32(sc[nt][3]);
        }
        __syncwarp();

        // ---- O += P @ V via mma ----
#pragma unroll
        for (int ks = 0; ks < 8; ++ks) {
            const int k0 = ks * 8 + kq;
            uint32_t a[4];
            a[0] = s.P[rl0][k0];
            a[1] = s.P[rl0 + 8][k0];
            a[2] = s.P[rl0][k0 + 4];
            a[3] = s.P[rl0 + 8][k0 + 4];
#pragma unroll
            for (int nt = 0; nt < 8; ++nt) {
                uint32_t b[2];
                b[0] = s.V[k0][nt * 8 + ng];
                b[1] = s.V[k0 + 4][nt * 8 + ng];
                mma_tf32(o[nt], a, b);
            }
        }
    }

    // ---- epilogue: rel_v + normalize + merged write ----
#pragma unroll
    for (int half = 0; half < 2; ++half) {
        const int rl = rl0 + 8 * half;
        const int tg = it * 64 + rl;
        const float l = lrow[half];
        float wm[16], sumw = 0.f;
#pragma unroll
        for (int m = 0; m < 16; ++m) { wm[m] = s.wsum[rl][m]; sumw += wm[m]; }
        const float w0 = l - sumw;
        const float inv = 1.f / l;
#pragma unroll
        for (int nt = 0; nt < 8; ++nt) {
            const int d0 = nt * 8 + 2 * kq;
            float acc0 = o[nt][half * 2 + 0] + w0 * s.pev[0][d0];
            float acc1 = o[nt][half * 2 + 1] + w0 * s.pev[0][d0 + 1];
#pragma unroll
            for (int m = 1; m <= 16; ++m) {
                acc0 = fmaf(wm[m - 1], s.pev[m][d0], acc0);
                acc1 = fmaf(wm[m - 1], s.pev[m][d0 + 1], acc1);
            }
            float2 ov = make_float2(acc0 * inv, acc1 * inv);
            *(float2*)&g_att[((size_t)(bidx * Tt) + tg) * Uu + h * DH + d0] = ov;
        }
    }
}

// ---------------------------------------------------------------------------
// LayerNorm over last dim (512), eps = 1e-3.  Reads g_proj device global.
// ---------------------------------------------------------------------------
__global__ __launch_bounds__(128) void ln_kernel(
    const float* __restrict__ gamma,
    const float* __restrict__ beta, float* __restrict__ out)
{
    const int row = blockIdx.x;
    const int tid = threadIdx.x;
    float4 v = *(const float4*)&g_proj[(size_t)row * Uu + tid * 4];
    float sum = v.x + v.y + v.z + v.w;
    float sq = v.x * v.x + v.y * v.y + v.z * v.z + v.w * v.w;
#pragma unroll
    for (int off = 16; off; off >>= 1) {
        sum += __shfl_xor_sync(0xffffffffu, sum, off);
        sq  += __shfl_xor_sync(0xffffffffu, sq, off);
    }
    __shared__ float red[8];
    int warp = tid >> 5, lane = tid & 31;
    if (lane == 0) { red[warp] = sum; red[4 + warp] = sq; }
    __syncthreads();
    sum = red[0] + red[1] + red[2] + red[3];
    sq  = red[4] + red[5] + red[6] + red[7];
    float mu = sum * (1.f / Uu);
    float var = sq * (1.f / Uu) - mu * mu;
    float rstd = rsqrtf(var + 1e-3f);
    float4 g = *(const float4*)&gamma[tid * 4];
    float4 be = *(const float4*)&beta[tid * 4];
    float4 o;
    o.x = (v.x - mu) * rstd * g.x + be.x;
    o.y = (v.y - mu) * rstd * g.y + be.y;
    o.z = (v.z - mu) * rstd * g.z + be.z;
    o.w = (v.w - mu) * rstd * g.w + be.w;
    *(float4*)&out[(size_t)row * Uu + tid * 4] = o;
}

// ---------------------------------------------------------------------------
// Input binding: detect permutation from in_sizes (sizes distinguish order).
// ---------------------------------------------------------------------------
extern "C" void kernel_launch(void* const* d_in, const int* in_sizes, int n_in,
                              void* d_out, int out_size) {
    (void)n_in; (void)out_size;

    int iq, ik, iv, iWq, ibq, iWk, ibk, iWv, ibv, iWo, ibo, ig, ibe, ipk, ipv;
    if (in_sizes[0] == Bb * Tt * Uu) {
        // insertion order
        iq = 0; ik = 1; iv = 2; iWq = 3; ibq = 4; iWk = 5; ibk = 6;
        iWv = 7; ibv = 8; iWo = 9; ibo = 10; ig = 11; ibe = 12; ipk = 13; ipv = 14;
    } else if (in_sizes[0] == Uu * Uu) {
        // ASCII sort (uppercase first)
        iWk = 0; iWo = 1; iWq = 2; iWv = 3; ibe = 4; ibk = 5; ibo = 6;
        ibq = 7; ibv = 8; ig = 9; ik = 10; ipk = 11; ipv = 12; iq = 13; iv = 14;
    } else {
        // case-insensitive sort
        ibe = 0; ibk = 1; ibo = 2; ibq = 3; ibv = 4; ig = 5; ik = 6;
        ipk = 7; ipv = 8; iq = 9; iv = 10; iWk = 11; iWo = 12; iWq = 13; iWv = 14;
    }

    const float* q    = (const float*)d_in[iq];
    const float* k    = (const float*)d_in[ik];
    const float* v    = (const float*)d_in[iv];
    const float* Wq   = (const float*)d_in[iWq];
    const float* bq   = (const float*)d_in[ibq];
    const float* Wk   = (const float*)d_in[iWk];
    const float* bk   = (const float*)d_in[ibk];
    const float* Wv   = (const float*)d_in[iWv];
    const float* bv   = (const float*)d_in[ibv];
    const float* Wo   = (const float*)d_in[iWo];
    const float* bo   = (const float*)d_in[ibo];
    const float* gamma= (const float*)d_in[ig];
    const float* beta = (const float*)d_in[ibe];
    const float* pek  = (const float*)d_in[ipk];
    const float* pev  = (const float*)d_in[ipv];
    float* out = (float*)d_out;

    cudaFuncSetAttribute(attn_kernel, cudaFuncAttributeMaxDynamicSharedMemorySize,
                         (int)sizeof(AttnSmem));

    float* g_qh_p;  cudaGetSymbolAddress((void**)&g_qh_p,  g_qh);
    float* g_kh_p;  cudaGetSymbolAddress((void**)&g_kh_p,  g_kh);
    float* g_vh_p;  cudaGetSymbolAddress((void**)&g_vh_p,  g_vh);
    float* g_att_p; cudaGetSymbolAddress((void**)&g_att_p, g_att);
    float* g_proj_p;cudaGetSymbolAddress((void**)&g_proj_p,g_proj);

    // Q/K/V projections (TF32 tensor cores), head-split output
    gemm_tf32<0><<<dim3(4, 64), 256>>>(q, Wq, bq, nullptr, g_qh_p);
    gemm_tf32<0><<<dim3(4, 64), 256>>>(k, Wk, bk, nullptr, g_kh_p);
    gemm_tf32<0><<<dim3(4, 64), 256>>>(v, Wv, bv, nullptr, g_vh_p);

    attn_kernel<<<dim3(16, 64), 128, sizeof(AttnSmem)>>>(pek, pev);

    // Output projection + relu + residual (TF32)
    gemm_tf32<1><<<dim3(4, 64), 256>>>(g_att_p, Wo, bo, q, g_proj_p);

    ln_kernel<<<MR, 128>>>(gamma, beta, out);
}

// round 6
// speedup vs baseline: 2.6491x; 1.0965x over previous
#include <cuda_runtime.h>
#include <math.h>
#include <stdint.h>

// Problem constants
static constexpr int Bb  = 8;
static constexpr int Tt  = 1024;
static constexpr int Uu  = 512;
static constexpr int DH  = 64;
static constexpr int HB  = 64;           // H*B
static constexpr int MR  = Bb * Tt;      // 8192 rows

// Scratch (device globals: allocation-free rule)
__device__ float g_qh[HB * Tt * DH];     // head-split q_emb [hb][t][d]
__device__ float g_kh[HB * Tt * DH];
__device__ float g_vh[HB * Tt * DH];
__device__ float g_att[MR * Uu];         // merged attention output [row][U]
__device__ float g_proj[MR * Uu];        // after out-proj + relu + residual

// ---------------------------------------------------------------------------
// TF32 helpers
// ---------------------------------------------------------------------------
__device__ __forceinline__ uint32_t f2tf32(float f) {
    uint32_t u;
    asm("cvt.rna.tf32.f32 %0, %1;" : "=r"(u) : "f"(f));
    return u;
}

__device__ __forceinline__ void mma_tf32(float c[4], const uint32_t a[4], const uint32_t b[2]) {
    asm volatile(
        "mma.sync.aligned.m16n8k8.row.col.f32.tf32.tf32.f32 "
        "{%0,%1,%2,%3}, {%4,%5,%6,%7}, {%8,%9}, {%0,%1,%2,%3};"
        : "+f"(c[0]), "+f"(c[1]), "+f"(c[2]), "+f"(c[3])
        : "r"(a[0]), "r"(a[1]), "r"(a[2]), "r"(a[3]), "r"(b[0]), "r"(b[1]));
}

__device__ __forceinline__ void cp16(uint32_t saddr, const void* gptr) {
    asm volatile("cp.async.cg.shared.global [%0], [%1], 16;" :: "r"(saddr), "l"(gptr));
}

// ---------------------------------------------------------------------------
// TF32 GEMM: 128x128 tile, BK=16, 256 threads (8 warps as 2x4, warp tile
// 64x32).  Double-buffered smem.  MODE 0: qkv projection (head-split output,
// relu+bias).  MODE 1: out projection (relu+bias+residual, row-major output).
// ---------------------------------------------------------------------------
template <int MODE>
__global__ __launch_bounds__(256) void gemm_tf32(
    const float* __restrict__ A, const float* __restrict__ W,
    const float* __restrict__ bias, const float* __restrict__ res,
    float* __restrict__ dst)
{
    __shared__ uint32_t As[2][128][20];   // [row][k], pad to 20
    __shared__ uint32_t Bs[2][16][136];   // [k][n], pad to 136

    const int tid  = threadIdx.x;
    const int lane = tid & 31;
    const int wid  = tid >> 5;
    const int wm   = wid >> 2;            // 0..1
    const int wn   = wid & 3;             // 0..3
    const int rowBase = blockIdx.y * 128;
    const int nBase   = blockIdx.x * 128;

    // loaders
    const int ar  = tid >> 2;             // 0..63  (rows ar, ar+64)
    const int ac4 = tid & 3;              // k-float4 0..3
    const int br  = tid >> 5;             // 0..7   (rows br, br+8)
    const int bc4 = tid & 31;             // n-float4 0..31

    float4 pa[2], pb[2];

    auto ldg = [&](int kb) {
        pa[0] = *(const float4*)&A[(size_t)(rowBase + ar) * Uu + kb + ac4 * 4];
        pa[1] = *(const float4*)&A[(size_t)(rowBase + ar + 64) * Uu + kb + ac4 * 4];
        pb[0] = *(const float4*)&W[(size_t)(kb + br) * Uu + nBase + bc4 * 4];
        pb[1] = *(const float4*)&W[(size_t)(kb + br + 8) * Uu + nBase + bc4 * 4];
    };
    auto sts = [&](int buf) {
#pragma unroll
        for (int i = 0; i < 2; ++i) {
            const float* p = &pa[i].x;
#pragma unroll
            for (int j = 0; j < 4; ++j)
                As[buf][ar + i * 64][ac4 * 4 + j] = f2tf32(p[j]);
            const float* q = &pb[i].x;
#pragma unroll
            for (int j = 0; j < 4; ++j)
                Bs[buf][br + i * 8][bc4 * 4 + j] = f2tf32(q[j]);
        }
    };

    float c[4][4][4] = {};   // [mt][nt][4]

    ldg(0);
    sts(0);
    __syncthreads();

    const int r0 = wm * 64 + (lane >> 2);
    const int n0 = wn * 32 + (lane >> 2);
    const int kq = lane & 3;

    for (int kb = 0; kb < Uu / 16; ++kb) {
        const int cur = kb & 1;
        if (kb + 1 < Uu / 16) ldg((kb + 1) * 16);

#pragma unroll
        for (int ks = 0; ks < 2; ++ks) {
            const int k0 = ks * 8 + kq;
            uint32_t a[4][4];
#pragma unroll
            for (int mt = 0; mt < 4; ++mt) {
                a[mt][0] = As[cur][r0 + mt * 16][k0];
                a[mt][1] = As[cur][r0 + mt * 16 + 8][k0];
                a[mt][2] = As[cur][r0 + mt * 16][k0 + 4];
                a[mt][3] = As[cur][r0 + mt * 16 + 8][k0 + 4];
            }
            uint32_t b[4][2];
#pragma unroll
            for (int nt = 0; nt < 4; ++nt) {
                b[nt][0] = Bs[cur][k0][n0 + nt * 8];
                b[nt][1] = Bs[cur][k0 + 4][n0 + nt * 8];
            }
#pragma unroll
            for (int mt = 0; mt < 4; ++mt)
#pragma unroll
                for (int nt = 0; nt < 4; ++nt)
                    mma_tf32(c[mt][nt], a[mt], b[nt]);
        }

        if (kb + 1 < Uu / 16) sts(cur ^ 1);
        __syncthreads();
    }

    // Epilogue
#pragma unroll
    for (int mt = 0; mt < 4; ++mt) {
        const int rbase = rowBase + wm * 64 + mt * 16 + (lane >> 2);
#pragma unroll
        for (int nt = 0; nt < 4; ++nt) {
            const int n = nBase + wn * 32 + nt * 8 + (lane & 3) * 2;
            const float2 bi = *(const float2*)&bias[n];
#pragma unroll
            for (int half = 0; half < 2; ++half) {
                const int m = rbase + half * 8;
                float2 o;
                o.x = fmaxf(c[mt][nt][half * 2 + 0] + bi.x, 0.f);
                o.y = fmaxf(c[mt][nt][half * 2 + 1] + bi.y, 0.f);
                if (MODE == 0) {
                    // head-split: dst[(h*8 + b)*1024 + t][d]
                    const int h = n >> 6, d = n & 63;
                    const int bidx = m >> 10, t = m & 1023;
                    *(float2*)&dst[((size_t)(h * 8 + bidx) * Tt + t) * DH + d] = o;
                } else {
                    const float2 r2 = *(const float2*)&res[(size_t)m * Uu + n];
                    o.x += r2.x;
                    o.y += r2.y;
                    *(float2*)&dst[(size_t)m * Uu + n] = o;
                }
            }
        }
    }
}

// ---------------------------------------------------------------------------
// Tensor-core flash attention, cp.async double-buffered K/V.
// One block per (q-tile 64, hb).  128 threads = 4 warps; warp w owns rows
// 16w..16w+15.  K/V/P fed to mma as raw fp32 bits (HW truncates to tf32).
// Overlays: pek on P (prologue only), pev on Q (epilogue only).
// ---------------------------------------------------------------------------
struct AttnSmem {
    uint32_t K[2][64][68];   // raw fp32 bits, [buf][key][d]
    uint32_t V[2][64][72];   // raw fp32 bits, [buf][key][d]
    union { uint32_t Q[64][68]; float pev[17][68]; };
    union { uint32_t P[64][68]; float pek[17][68]; };
    float qrel[64][17];
    float wsum[64][16];
};

__global__ __launch_bounds__(128) void attn_kernel(
    const float* __restrict__ pe_k, const float* __restrict__ pe_v)
{
    extern __shared__ __align__(16) char smem_raw[];
    AttnSmem& s = *reinterpret_cast<AttnSmem*>(smem_raw);

    const int tid  = threadIdx.x;
    const int lane = tid & 31;
    const int w    = tid >> 5;
    const int kq   = lane & 3;
    const int ng   = lane >> 2;
    const int it   = 15 - (int)blockIdx.x;   // heavy tiles first
    const int hb   = blockIdx.y;
    const int h = hb >> 3, bidx = hb & 7;

    const float* qbase = g_qh + (size_t)hb * Tt * DH;
    const float* kbase = g_kh + (size_t)hb * Tt * DH;
    const float* vbase = g_vh + (size_t)hb * Tt * DH;

    const uint32_t kS = (uint32_t)__cvta_generic_to_shared(&s.K[0][0][0]);
    const uint32_t vS = (uint32_t)__cvta_generic_to_shared(&s.V[0][0][0]);

    auto issue_tile = [&](int buf, int jt) {
#pragma unroll
        for (int ii = 0; ii < 8; ++ii) {
            const int i = tid + ii * 128;
            const int c = i >> 4, dq = i & 15;
            cp16(kS + (((buf * 64 + c) * 68 + dq * 4) << 2),
                 &kbase[(size_t)(jt * 64 + c) * DH + dq * 4]);
            cp16(vS + (((buf * 64 + c) * 72 + dq * 4) << 2),
                 &vbase[(size_t)(jt * 64 + c) * DH + dq * 4]);
        }
        asm volatile("cp.async.commit_group;");
    };

    // Kick off tile 0 immediately
    issue_tile(0, 0);

    // Load Q tile (scaled by 1/8, tf32-rounded) + pek (overlaid on P)
    for (int i = tid; i < 1024; i += 128) {
        int r = i >> 4, dq = i & 15;
        float4 a = *(const float4*)&qbase[(size_t)(it * 64 + r) * DH + dq * 4];
        s.Q[r][dq * 4 + 0] = f2tf32(a.x * 0.125f);
        s.Q[r][dq * 4 + 1] = f2tf32(a.y * 0.125f);
        s.Q[r][dq * 4 + 2] = f2tf32(a.z * 0.125f);
        s.Q[r][dq * 4 + 3] = f2tf32(a.w * 0.125f);
    }
    for (int i = tid; i < 17 * 16; i += 128) {
        int m = i / 16, dq = i % 16;
        *(float4*)&s.pek[m][dq * 4] = *(const float4*)&pe_k[m * DH + dq * 4];
    }
    for (int i = tid; i < 1024; i += 128)
        (&s.wsum[0][0])[i] = 0.f;
    __syncthreads();

    // qrel[r][m] = (q/8) . pe_k[m]
    for (int i = tid; i < 64 * 17; i += 128) {
        int r = i / 17, m = i % 17;
        float acc = 0.f;
#pragma unroll 16
        for (int d = 0; d < DH; ++d)
            acc = fmaf(__uint_as_float(s.Q[r][d]), s.pek[m][d], acc);
        s.qrel[r][m] = acc;
    }
    __syncthreads();   // pek region (P) free after this

    const int rl0 = w * 16 + ng;
    const float qrel0_0 = s.qrel[rl0][0];
    const float qrel0_1 = s.qrel[rl0 + 8][0];

    float o[8][4] = {};
    float mrow[2] = {-1e30f, -1e30f};
    float lrow[2] = {};

    for (int jt = 0; jt <= it; ++jt) {
        const int cur = jt & 1;
        if (jt < it) {
            issue_tile(cur ^ 1, jt + 1);
            asm volatile("cp.async.wait_group 1;");
        } else {
            asm volatile("cp.async.wait_group 0;");
        }
        __syncthreads();

        // ---- S = (Q/8) @ K^T via mma ----
        float sc[8][4] = {};
#pragma unroll
        for (int ks = 0; ks < 8; ++ks) {
            const int k0 = ks * 8 + kq;
            uint32_t a[4];
            a[0] = s.Q[rl0][k0];
            a[1] = s.Q[rl0 + 8][k0];
            a[2] = s.Q[rl0][k0 + 4];
            a[3] = s.Q[rl0 + 8][k0 + 4];
#pragma unroll
            for (int nt = 0; nt < 8; ++nt) {
                uint32_t b[2];
                b[0] = s.K[cur][nt * 8 + ng][k0];
                b[1] = s.K[cur][nt * 8 + ng][k0 + 4];
                mma_tf32(sc[nt], a, b);
            }
        }

        // ---- rel_k bias (+ causal mask on near tiles) ----
        const bool near = (jt >= it - 1);
        if (near) {
#pragma unroll
            for (int nt = 0; nt < 8; ++nt) {
#pragma unroll
                for (int ci = 0; ci < 4; ++ci) {
                    const int row_l = rl0 + ((ci >> 1) << 3);
                    const int tg = it * 64 + row_l;
                    const int sg = jt * 64 + nt * 8 + 2 * kq + (ci & 1);
                    const int delta = sg - tg;
                    if (delta > 0) sc[nt][ci] = -1e30f;
                    else {
                        int mi = delta + 16; if (mi < 0) mi = 0;
                        sc[nt][ci] += s.qrel[row_l][mi];
                    }
                }
            }
        } else {
#pragma unroll
            for (int nt = 0; nt < 8; ++nt) {
                sc[nt][0] += qrel0_0;
                sc[nt][1] += qrel0_0;
                sc[nt][2] += qrel0_1;
                sc[nt][3] += qrel0_1;
            }
        }

        // ---- online softmax ----
        float mt0 = -1e30f, mt1 = -1e30f;
#pragma unroll
        for (int nt = 0; nt < 8; ++nt) {
            mt0 = fmaxf(mt0, fmaxf(sc[nt][0], sc[nt][1]));
            mt1 = fmaxf(mt1, fmaxf(sc[nt][2], sc[nt][3]));
        }
        mt0 = fmaxf(mt0, __shfl_xor_sync(0xffffffffu, mt0, 1));
        mt0 = fmaxf(mt0, __shfl_xor_sync(0xffffffffu, mt0, 2));
        mt1 = fmaxf(mt1, __shfl_xor_sync(0xffffffffu, mt1, 1));
        mt1 = fmaxf(mt1, __shfl_xor_sync(0xffffffffu, mt1, 2));

        const float mnew0 = fmaxf(mrow[0], mt0);
        const float mnew1 = fmaxf(mrow[1], mt1);
        const float alpha0 = __expf(mrow[0] - mnew0);
        const float alpha1 = __expf(mrow[1] - mnew1);
        mrow[0] = mnew0; mrow[1] = mnew1;

        float ps0 = 0.f, ps1 = 0.f;
#pragma unroll
        for (int nt = 0; nt < 8; ++nt) {
            sc[nt][0] = __expf(sc[nt][0] - mnew0);
            sc[nt][1] = __expf(sc[nt][1] - mnew0);
            sc[nt][2] = __expf(sc[nt][2] - mnew1);
            sc[nt][3] = __expf(sc[nt][3] - mnew1);
            ps0 += sc[nt][0] + sc[nt][1];
            ps1 += sc[nt][2] + sc[nt][3];
        }
        ps0 += __shfl_xor_sync(0xffffffffu, ps0, 1);
        ps0 += __shfl_xor_sync(0xffffffffu, ps0, 2);
        ps1 += __shfl_xor_sync(0xffffffffu, ps1, 1);
        ps1 += __shfl_xor_sync(0xffffffffu, ps1, 2);
        lrow[0] = lrow[0] * alpha0 + ps0;
        lrow[1] = lrow[1] * alpha1 + ps1;

#pragma unroll
        for (int nt = 0; nt < 8; ++nt) {
            o[nt][0] *= alpha0; o[nt][1] *= alpha0;
            o[nt][2] *= alpha1; o[nt][3] *= alpha1;
        }

        // ---- wsum bookkeeping (warp-private rows) ----
#pragma unroll
        for (int j = 0; j < 4; ++j) {
            s.wsum[rl0][kq * 4 + j]     *= alpha0;
            s.wsum[rl0 + 8][kq * 4 + j] *= alpha1;
        }
        __syncwarp();
        if (near) {
#pragma unroll
            for (int nt = 0; nt < 8; ++nt) {
#pragma unroll
                for (int ci = 0; ci < 4; ++ci) {
                    const int row_l = rl0 + ((ci >> 1) << 3);
                    const int delta = (jt * 64 + nt * 8 + 2 * kq + (ci & 1)) - (it * 64 + row_l);
                    if (delta >= -15 && delta <= 0)
                        s.wsum[row_l][delta + 15] += sc[nt][ci];
                }
            }
        }
        __syncwarp();

        // ---- P -> smem (raw bits; mma truncates), warp-private rows ----
#pragma unroll
        for (int nt = 0; nt < 8; ++nt) {
            const int c0 = nt * 8 + 2 * kq;
            s.P[rl0][c0]         = __float_as_uint(sc[nt][0]);
            s.P[rl0][c0 + 1]     = __float_as_uint(sc[nt][1]);
            s.P[rl0 + 8][c0]     = __float_as_uint(sc[nt][2]);
            s.P[rl0 + 8][c0 + 1] = __float_as_uint(sc[nt][3]);
        }
        __syncwarp();

        // ---- O += P @ V via mma ----
#pragma unroll
        for (int ks = 0; ks < 8; ++ks) {
            const int k0 = ks * 8 + kq;
            uint32_t a[4];
            a[0] = s.P[rl0][k0];
            a[1] = s.P[rl0 + 8][k0];
            a[2] = s.P[rl0][k0 + 4];
            a[3] = s.P[rl0 + 8][k0 + 4];
#pragma unroll
            for (int nt = 0; nt < 8; ++nt) {
                uint32_t b[2];
                b[0] = s.V[cur][k0][nt * 8 + ng];
                b[1] = s.V[cur][k0 + 4][nt * 8 + ng];
                mma_tf32(o[nt], a, b);
            }
        }
        __syncthreads();   // all reads of buf `cur` done before it is re-filled
    }

    // ---- load pev (overlays Q; Q is dead now) ----
    for (int i = tid; i < 17 * 16; i += 128) {
        int m = i / 16, dq = i % 16;
        *(float4*)&s.pev[m][dq * 4] = *(const float4*)&pe_v[m * DH + dq * 4];
    }
    __syncthreads();

    // ---- epilogue: rel_v + normalize + merged write ----
#pragma unroll
    for (int half = 0; half < 2; ++half) {
        const int rl = rl0 + 8 * half;
        const int tg = it * 64 + rl;
        const float l = lrow[half];
        float wm[16], sumw = 0.f;
#pragma unroll
        for (int m = 0; m < 16; ++m) { wm[m] = s.wsum[rl][m]; sumw += wm[m]; }
        const float w0 = l - sumw;
        const float inv = 1.f / l;
#pragma unroll
        for (int nt = 0; nt < 8; ++nt) {
            const int d0 = nt * 8 + 2 * kq;
            float acc0 = o[nt][half * 2 + 0] + w0 * s.pev[0][d0];
            float acc1 = o[nt][half * 2 + 1] + w0 * s.pev[0][d0 + 1];
#pragma unroll
            for (int m = 1; m <= 16; ++m) {
                acc0 = fmaf(wm[m - 1], s.pev[m][d0], acc0);
                acc1 = fmaf(wm[m - 1], s.pev[m][d0 + 1], acc1);
            }
            float2 ov = make_float2(acc0 * inv, acc1 * inv);
            *(float2*)&g_att[((size_t)(bidx * Tt) + tg) * Uu + h * DH + d0] = ov;
        }
    }
}

// ---------------------------------------------------------------------------
// LayerNorm over last dim (512), eps = 1e-3.  Reads g_proj device global.
// ---------------------------------------------------------------------------
__global__ __launch_bounds__(128) void ln_kernel(
    const float* __restrict__ gamma,
    const float* __restrict__ beta, float* __restrict__ out)
{
    const int row = blockIdx.x;
    const int tid = threadIdx.x;
    float4 v = *(const float4*)&g_proj[(size_t)row * Uu + tid * 4];
    float sum = v.x + v.y + v.z + v.w;
    float sq = v.x * v.x + v.y * v.y + v.z * v.z + v.w * v.w;
#pragma unroll
    for (int off = 16; off; off >>= 1) {
        sum += __shfl_xor_sync(0xffffffffu, sum, off);
        sq  += __shfl_xor_sync(0xffffffffu, sq, off);
    }
    __shared__ float red[8];
    int warp = tid >> 5, lane = tid & 31;
    if (lane == 0) { red[warp] = sum; red[4 + warp] = sq; }
    __syncthreads();
    sum = red[0] + red[1] + red[2] + red[3];
    sq  = red[4] + red[5] + red[6] + red[7];
    float mu = sum * (1.f / Uu);
    float var = sq * (1.f / Uu) - mu * mu;
    float rstd = rsqrtf(var + 1e-3f);
    float4 g = *(const float4*)&gamma[tid * 4];
    float4 be = *(const float4*)&beta[tid * 4];
    float4 o;
    o.x = (v.x - mu) * rstd * g.x + be.x;
    o.y = (v.y - mu) * rstd * g.y + be.y;
    o.z = (v.z - mu) * rstd * g.z + be.z;
    o.w = (v.w - mu) * rstd * g.w + be.w;
    *(float4*)&out[(size_t)row * Uu + tid * 4] = o;
}

// ---------------------------------------------------------------------------
// Input binding: detect permutation from in_sizes (sizes distinguish order).
// ---------------------------------------------------------------------------
extern "C" void kernel_launch(void* const* d_in, const int* in_sizes, int n_in,
                              void* d_out, int out_size) {
    (void)n_in; (void)out_size;

    int iq, ik, iv, iWq, ibq, iWk, ibk, iWv, ibv, iWo, ibo, ig, ibe, ipk, ipv;
    if (in_sizes[0] == Bb * Tt * Uu) {
        // insertion order
        iq = 0; ik = 1; iv = 2; iWq = 3; ibq = 4; iWk = 5; ibk = 6;
        iWv = 7; ibv = 8; iWo = 9; ibo = 10; ig = 11; ibe = 12; ipk = 13; ipv = 14;
    } else if (in_sizes[0] == Uu * Uu) {
        // ASCII sort (uppercase first)
        iWk = 0; iWo = 1; iWq = 2; iWv = 3; ibe = 4; ibk = 5; ibo = 6;
        ibq = 7; ibv = 8; ig = 9; ik = 10; ipk = 11; ipv = 12; iq = 13; iv = 14;
    } else {
        // case-insensitive sort
        ibe = 0; ibk = 1; ibo = 2; ibq = 3; ibv = 4; ig = 5; ik = 6;
        ipk = 7; ipv = 8; iq = 9; iv = 10; iWk = 11; iWo = 12; iWq = 13; iWv = 14;
    }

    const float* q    = (const float*)d_in[iq];
    const float* k    = (const float*)d_in[ik];
    const float* v    = (const float*)d_in[iv];
    const float* Wq   = (const float*)d_in[iWq];
    const float* bq   = (const float*)d_in[ibq];
    const float* Wk   = (const float*)d_in[iWk];
    const float* bk   = (const float*)d_in[ibk];
    const float* Wv   = (const float*)d_in[iWv];
    const float* bv   = (const float*)d_in[ibv];
    const float* Wo   = (const float*)d_in[iWo];
    const float* bo   = (const float*)d_in[ibo];
    const float* gamma= (const float*)d_in[ig];
    const float* beta = (const float*)d_in[ibe];
    const float* pek  = (const float*)d_in[ipk];
    const float* pev  = (const float*)d_in[ipv];
    float* out = (float*)d_out;

    cudaFuncSetAttribute(attn_kernel, cudaFuncAttributeMaxDynamicSharedMemorySize,
                         (int)sizeof(AttnSmem));

    float* g_qh_p;  cudaGetSymbolAddress((void**)&g_qh_p,  g_qh);
    float* g_kh_p;  cudaGetSymbolAddress((void**)&g_kh_p,  g_kh);
    float* g_vh_p;  cudaGetSymbolAddress((void**)&g_vh_p,  g_vh);
    float* g_att_p; cudaGetSymbolAddress((void**)&g_att_p, g_att);
    float* g_proj_p;cudaGetSymbolAddress((void**)&g_proj_p,g_proj);

    // Q/K/V projections (TF32 tensor cores), head-split output
    gemm_tf32<0><<<dim3(4, 64), 256>>>(q, Wq, bq, nullptr, g_qh_p);
    gemm_tf32<0><<<dim3(4, 64), 256>>>(k, Wk, bk, nullptr, g_kh_p);
    gemm_tf32<0><<<dim3(4, 64), 256>>>(v, Wv, bv, nullptr, g_vh_p);

    attn_kernel<<<dim3(16, 64), 128, sizeof(AttnSmem)>>>(pek, pev);

    // Output projection + relu + residual (TF32)
    gemm_tf32<1><<<dim3(4, 64), 256>>>(g_att_p, Wo, bo, q, g_proj_p);

    ln_kernel<<<MR, 128>>>(gamma, beta, out);
}

// round 7
// speedup vs baseline: 2.9772x; 1.1238x over previous
#include <cuda_runtime.h>
#include <math.h>
#include <stdint.h>

// Problem constants
static constexpr int Bb  = 8;
static constexpr int Tt  = 1024;
static constexpr int Uu  = 512;
static constexpr int DH  = 64;
static constexpr int HB  = 64;           // H*B
static constexpr int MR  = Bb * Tt;      // 8192 rows

// Scratch (device globals: allocation-free rule)
__device__ float g_qh[HB * Tt * DH];     // head-split q_emb [hb][t][d]
__device__ float g_kh[HB * Tt * DH];
__device__ float g_vh[HB * Tt * DH];
__device__ float g_att[MR * Uu];         // merged attention output [row][U]
__device__ float g_proj[MR * Uu];        // after out-proj + relu + residual

// ---------------------------------------------------------------------------
// TF32 helpers
// ---------------------------------------------------------------------------
__device__ __forceinline__ uint32_t f2tf32(float f) {
    uint32_t u;
    asm("cvt.rna.tf32.f32 %0, %1;" : "=r"(u) : "f"(f));
    return u;
}

__device__ __forceinline__ void mma_tf32(float c[4], const uint32_t a[4], const uint32_t b[2]) {
    asm volatile(
        "mma.sync.aligned.m16n8k8.row.col.f32.tf32.tf32.f32 "
        "{%0,%1,%2,%3}, {%4,%5,%6,%7}, {%8,%9}, {%0,%1,%2,%3};"
        : "+f"(c[0]), "+f"(c[1]), "+f"(c[2]), "+f"(c[3])
        : "r"(a[0]), "r"(a[1]), "r"(a[2]), "r"(a[3]), "r"(b[0]), "r"(b[1]));
}

__device__ __forceinline__ void cp16(uint32_t saddr, const void* gptr) {
    asm volatile("cp.async.cg.shared.global [%0], [%1], 16;" :: "r"(saddr), "l"(gptr));
}

// ---------------------------------------------------------------------------
// TF32 GEMM, 4-stage cp.async pipeline.  128x128 tile, BK=16, 256 threads
// (8 warps 2x4, warp tile 64x32).  cvt.rna at fragment load.
// MODE 0: qkv projection (z selects q/k/v; head-split output, relu+bias).
// MODE 1: out projection (relu+bias+residual, row-major into g_proj).
// ---------------------------------------------------------------------------
struct GemmSmem {
    float As[4][128][20];   // [stage][row][k]  (stride 20: conflict-free a-frags)
    float Bs[4][16][136];   // [stage][k][n]    (stride 136: conflict-free b-frags)
};

template <int MODE>
__global__ __launch_bounds__(256, 2) void gemm_tf32(
    const float* __restrict__ q, const float* __restrict__ k, const float* __restrict__ v,
    const float* __restrict__ Wq, const float* __restrict__ Wk, const float* __restrict__ Wv,
    const float* __restrict__ bq, const float* __restrict__ bk, const float* __restrict__ bv,
    const float* __restrict__ res)
{
    extern __shared__ __align__(16) char smem_raw[];
    GemmSmem& sm = *reinterpret_cast<GemmSmem*>(smem_raw);

    const float* A; const float* W; const float* bias;
    if (MODE == 0) {
        const int z = blockIdx.z;
        A    = (z == 0) ? q  : (z == 1) ? k  : v;
        W    = (z == 0) ? Wq : (z == 1) ? Wk : Wv;
        bias = (z == 0) ? bq : (z == 1) ? bk : bv;
    } else {
        A = q; W = Wq; bias = bq;   // (g_att is read via q slot? no: MODE1 passes A=g_att ptr)
    }

    const int tid  = threadIdx.x;
    const int lane = tid & 31;
    const int wid  = tid >> 5;
    const int wm   = wid >> 2;            // 0..1
    const int wn   = wid & 3;             // 0..3
    const int rowBase = blockIdx.y * 128;
    const int nBase   = blockIdx.x * 128;

    const uint32_t aS = (uint32_t)__cvta_generic_to_shared(&sm.As[0][0][0]);
    const uint32_t bS = (uint32_t)__cvta_generic_to_shared(&sm.Bs[0][0][0]);

    auto issue = [&](int s, int kt) {
        const int kb = kt * 16;
#pragma unroll
        for (int ii = 0; ii < 2; ++ii) {
            const int idx = tid + ii * 256;
            const int row = idx >> 2, q4 = idx & 3;
            cp16(aS + (((s * 128 + row) * 20 + q4 * 4) << 2),
                 &A[(size_t)(rowBase + row) * Uu + kb + q4 * 4]);
        }
#pragma unroll
        for (int ii = 0; ii < 2; ++ii) {
            const int idx = tid + ii * 256;
            const int kr = idx >> 5, n4 = idx & 31;
            cp16(bS + (((s * 16 + kr) * 136 + n4 * 4) << 2),
                 &W[(size_t)(kb + kr) * Uu + nBase + n4 * 4]);
        }
    };

    constexpr int NIT = Uu / 16;   // 32

    // Prologue: 3 stages in flight
    issue(0, 0); asm volatile("cp.async.commit_group;");
    issue(1, 1); asm volatile("cp.async.commit_group;");
    issue(2, 2); asm volatile("cp.async.commit_group;");
    asm volatile("cp.async.wait_group 2;");
    __syncthreads();

    const int r0 = wm * 64 + (lane >> 2);
    const int n0 = wn * 32 + (lane >> 2);
    const int kq = lane & 3;

    float c[4][4][4] = {};   // [mt][nt][4]

    for (int kb = 0; kb < NIT; ++kb) {
        const int cur = kb & 3;
        if (kb + 3 < NIT) issue((kb + 3) & 3, kb + 3);
        asm volatile("cp.async.commit_group;");

#pragma unroll
        for (int ks = 0; ks < 2; ++ks) {
            const int k0 = ks * 8 + kq;
            uint32_t a[4][4];
#pragma unroll
            for (int mt = 0; mt < 4; ++mt) {
                a[mt][0] = f2tf32(sm.As[cur][r0 + mt * 16][k0]);
                a[mt][1] = f2tf32(sm.As[cur][r0 + mt * 16 + 8][k0]);
                a[mt][2] = f2tf32(sm.As[cur][r0 + mt * 16][k0 + 4]);
                a[mt][3] = f2tf32(sm.As[cur][r0 + mt * 16 + 8][k0 + 4]);
            }
            uint32_t b[4][2];
#pragma unroll
            for (int nt = 0; nt < 4; ++nt) {
                b[nt][0] = f2tf32(sm.Bs[cur][k0][n0 + nt * 8]);
                b[nt][1] = f2tf32(sm.Bs[cur][k0 + 4][n0 + nt * 8]);
            }
#pragma unroll
            for (int mt = 0; mt < 4; ++mt)
#pragma unroll
                for (int nt = 0; nt < 4; ++nt)
                    mma_tf32(c[mt][nt], a[mt], b[nt]);
        }

        asm volatile("cp.async.wait_group 2;");
        __syncthreads();
    }

    // Epilogue
    float* dst;
    if (MODE == 0) {
        const int z = blockIdx.z;
        dst = (z == 0) ? g_qh : (z == 1) ? g_kh : g_vh;
    } else {
        dst = g_proj;
    }

#pragma unroll
    for (int mt = 0; mt < 4; ++mt) {
        const int rbase = rowBase + wm * 64 + mt * 16 + (lane >> 2);
#pragma unroll
        for (int nt = 0; nt < 4; ++nt) {
            const int n = nBase + wn * 32 + nt * 8 + (lane & 3) * 2;
            const float2 bi = *(const float2*)&bias[n];
#pragma unroll
            for (int half = 0; half < 2; ++half) {
                const int m = rbase + half * 8;
                float2 o;
                o.x = fmaxf(c[mt][nt][half * 2 + 0] + bi.x, 0.f);
                o.y = fmaxf(c[mt][nt][half * 2 + 1] + bi.y, 0.f);
                if (MODE == 0) {
                    // head-split: dst[(h*8 + b)*1024 + t][d]
                    const int h = n >> 6, d = n & 63;
                    const int bidx = m >> 10, t = m & 1023;
                    *(float2*)&dst[((size_t)(h * 8 + bidx) * Tt + t) * DH + d] = o;
                } else {
                    const float2 r2 = *(const float2*)&res[(size_t)m * Uu + n];
                    o.x += r2.x;
                    o.y += r2.y;
                    *(float2*)&dst[(size_t)m * Uu + n] = o;
                }
            }
        }
    }
}

// ---------------------------------------------------------------------------
// Tensor-core flash attention, cp.async double-buffered K/V (unchanged from
// the validated round-6 kernel).
// ---------------------------------------------------------------------------
struct AttnSmem {
    uint32_t K[2][64][68];   // raw fp32 bits, [buf][key][d]
    uint32_t V[2][64][72];   // raw fp32 bits, [buf][key][d]
    union { uint32_t Q[64][68]; float pev[17][68]; };
    union { uint32_t P[64][68]; float pek[17][68]; };
    float qrel[64][17];
    float wsum[64][16];
};

__global__ __launch_bounds__(128) void attn_kernel(
    const float* __restrict__ pe_k, const float* __restrict__ pe_v)
{
    extern __shared__ __align__(16) char smem_raw[];
    AttnSmem& s = *reinterpret_cast<AttnSmem*>(smem_raw);

    const int tid  = threadIdx.x;
    const int lane = tid & 31;
    const int w    = tid >> 5;
    const int kq   = lane & 3;
    const int ng   = lane >> 2;
    const int it   = 15 - (int)blockIdx.x;   // heavy tiles first
    const int hb   = blockIdx.y;
    const int h = hb >> 3, bidx = hb & 7;

    const float* qbase = g_qh + (size_t)hb * Tt * DH;
    const float* kbase = g_kh + (size_t)hb * Tt * DH;
    const float* vbase = g_vh + (size_t)hb * Tt * DH;

    const uint32_t kS = (uint32_t)__cvta_generic_to_shared(&s.K[0][0][0]);
    const uint32_t vS = (uint32_t)__cvta_generic_to_shared(&s.V[0][0][0]);

    auto issue_tile = [&](int buf, int jt) {
#pragma unroll
        for (int ii = 0; ii < 8; ++ii) {
            const int i = tid + ii * 128;
            const int c = i >> 4, dq = i & 15;
            cp16(kS + (((buf * 64 + c) * 68 + dq * 4) << 2),
                 &kbase[(size_t)(jt * 64 + c) * DH + dq * 4]);
            cp16(vS + (((buf * 64 + c) * 72 + dq * 4) << 2),
                 &vbase[(size_t)(jt * 64 + c) * DH + dq * 4]);
        }
        asm volatile("cp.async.commit_group;");
    };

    issue_tile(0, 0);

    for (int i = tid; i < 1024; i += 128) {
        int r = i >> 4, dq = i & 15;
        float4 a = *(const float4*)&qbase[(size_t)(it * 64 + r) * DH + dq * 4];
        s.Q[r][dq * 4 + 0] = f2tf32(a.x * 0.125f);
        s.Q[r][dq * 4 + 1] = f2tf32(a.y * 0.125f);
        s.Q[r][dq * 4 + 2] = f2tf32(a.z * 0.125f);
        s.Q[r][dq * 4 + 3] = f2tf32(a.w * 0.125f);
    }
    for (int i = tid; i < 17 * 16; i += 128) {
        int m = i / 16, dq = i % 16;
        *(float4*)&s.pek[m][dq * 4] = *(const float4*)&pe_k[m * DH + dq * 4];
    }
    for (int i = tid; i < 1024; i += 128)
        (&s.wsum[0][0])[i] = 0.f;
    __syncthreads();

    for (int i = tid; i < 64 * 17; i += 128) {
        int r = i / 17, m = i % 17;
        float acc = 0.f;
#pragma unroll 16
        for (int d = 0; d < DH; ++d)
            acc = fmaf(__uint_as_float(s.Q[r][d]), s.pek[m][d], acc);
        s.qrel[r][m] = acc;
    }
    __syncthreads();   // pek region (P) free after this

    const int rl0 = w * 16 + ng;
    const float qrel0_0 = s.qrel[rl0][0];
    const float qrel0_1 = s.qrel[rl0 + 8][0];

    float o[8][4] = {};
    float mrow[2] = {-1e30f, -1e30f};
    float lrow[2] = {};

    for (int jt = 0; jt <= it; ++jt) {
        const int cur = jt & 1;
        if (jt < it) {
            issue_tile(cur ^ 1, jt + 1);
            asm volatile("cp.async.wait_group 1;");
        } else {
            asm volatile("cp.async.wait_group 0;");
        }
        __syncthreads();

        float sc[8][4] = {};
#pragma unroll
        for (int ks = 0; ks < 8; ++ks) {
            const int k0 = ks * 8 + kq;
            uint32_t a[4];
            a[0] = s.Q[rl0][k0];
            a[1] = s.Q[rl0 + 8][k0];
            a[2] = s.Q[rl0][k0 + 4];
            a[3] = s.Q[rl0 + 8][k0 + 4];
#pragma unroll
            for (int nt = 0; nt < 8; ++nt) {
                uint32_t b[2];
                b[0] = s.K[cur][nt * 8 + ng][k0];
                b[1] = s.K[cur][nt * 8 + ng][k0 + 4];
                mma_tf32(sc[nt], a, b);
            }
        }

        const bool near = (jt >= it - 1);
        if (near) {
#pragma unroll
            for (int nt = 0; nt < 8; ++nt) {
#pragma unroll
                for (int ci = 0; ci < 4; ++ci) {
                    const int row_l = rl0 + ((ci >> 1) << 3);
                    const int tg = it * 64 + row_l;
                    const int sg = jt * 64 + nt * 8 + 2 * kq + (ci & 1);
                    const int delta = sg - tg;
                    if (delta > 0) sc[nt][ci] = -1e30f;
                    else {
                        int mi = delta + 16; if (mi < 0) mi = 0;
                        sc[nt][ci] += s.qrel[row_l][mi];
                    }
                }
            }
        } else {
#pragma unroll
            for (int nt = 0; nt < 8; ++nt) {
                sc[nt][0] += qrel0_0;
                sc[nt][1] += qrel0_0;
                sc[nt][2] += qrel0_1;
                sc[nt][3] += qrel0_1;
            }
        }

        float mt0 = -1e30f, mt1 = -1e30f;
#pragma unroll
        for (int nt = 0; nt < 8; ++nt) {
            mt0 = fmaxf(mt0, fmaxf(sc[nt][0], sc[nt][1]));
            mt1 = fmaxf(mt1, fmaxf(sc[nt][2], sc[nt][3]));
        }
        mt0 = fmaxf(mt0, __shfl_xor_sync(0xffffffffu, mt0, 1));
        mt0 = fmaxf(mt0, __shfl_xor_sync(0xffffffffu, mt0, 2));
        mt1 = fmaxf(mt1, __shfl_xor_sync(0xffffffffu, mt1, 1));
        mt1 = fmaxf(mt1, __shfl_xor_sync(0xffffffffu, mt1, 2));

        const float mnew0 = fmaxf(mrow[0], mt0);
        const float mnew1 = fmaxf(mrow[1], mt1);
        const float alpha0 = __expf(mrow[0] - mnew0);
        const float alpha1 = __expf(mrow[1] - mnew1);
        mrow[0] = mnew0; mrow[1] = mnew1;

        float ps0 = 0.f, ps1 = 0.f;
#pragma unroll
        for (int nt = 0; nt < 8; ++nt) {
            sc[nt][0] = __expf(sc[nt][0] - mnew0);
            sc[nt][1] = __expf(sc[nt][1] - mnew0);
            sc[nt][2] = __expf(sc[nt][2] - mnew1);
            sc[nt][3] = __expf(sc[nt][3] - mnew1);
            ps0 += sc[nt][0] + sc[nt][1];
            ps1 += sc[nt][2] + sc[nt][3];
        }
        ps0 += __shfl_xor_sync(0xffffffffu, ps0, 1);
        ps0 += __shfl_xor_sync(0xffffffffu, ps0, 2);
        ps1 += __shfl_xor_sync(0xffffffffu, ps1, 1);
        ps1 += __shfl_xor_sync(0xffffffffu, ps1, 2);
        lrow[0] = lrow[0] * alpha0 + ps0;
        lrow[1] = lrow[1] * alpha1 + ps1;

#pragma unroll
        for (int nt = 0; nt < 8; ++nt) {
            o[nt][0] *= alpha0; o[nt][1] *= alpha0;
            o[nt][2] *= alpha1; o[nt][3] *= alpha1;
        }

#pragma unroll
        for (int j = 0; j < 4; ++j) {
            s.wsum[rl0][kq * 4 + j]     *= alpha0;
            s.wsum[rl0 + 8][kq * 4 + j] *= alpha1;
        }
        __syncwarp();
        if (near) {
#pragma unroll
            for (int nt = 0; nt < 8; ++nt) {
#pragma unroll
                for (int ci = 0; ci < 4; ++ci) {
                    const int row_l = rl0 + ((ci >> 1) << 3);
                    const int delta = (jt * 64 + nt * 8 + 2 * kq + (ci & 1)) - (it * 64 + row_l);
                    if (delta >= -15 && delta <= 0)
                        s.wsum[row_l][delta + 15] += sc[nt][ci];
                }
            }
        }
        __syncwarp();

#pragma unroll
        for (int nt = 0; nt < 8; ++nt) {
            const int c0 = nt * 8 + 2 * kq;
            s.P[rl0][c0]         = __float_as_uint(sc[nt][0]);
            s.P[rl0][c0 + 1]     = __float_as_uint(sc[nt][1]);
            s.P[rl0 + 8][c0]     = __float_as_uint(sc[nt][2]);
            s.P[rl0 + 8][c0 + 1] = __float_as_uint(sc[nt][3]);
        }
        __syncwarp();

#pragma unroll
        for (int ks = 0; ks < 8; ++ks) {
            const int k0 = ks * 8 + kq;
            uint32_t a[4];
            a[0] = s.P[rl0][k0];
            a[1] = s.P[rl0 + 8][k0];
            a[2] = s.P[rl0][k0 + 4];
            a[3] = s.P[rl0 + 8][k0 + 4];
#pragma unroll
            for (int nt = 0; nt < 8; ++nt) {
                uint32_t b[2];
                b[0] = s.V[cur][k0][nt * 8 + ng];
                b[1] = s.V[cur][k0 + 4][nt * 8 + ng];
                mma_tf32(o[nt], a, b);
            }
        }
        __syncthreads();
    }

    for (int i = tid; i < 17 * 16; i += 128) {
        int m = i / 16, dq = i % 16;
        *(float4*)&s.pev[m][dq * 4] = *(const float4*)&pe_v[m * DH + dq * 4];
    }
    __syncthreads();

#pragma unroll
    for (int half = 0; half < 2; ++half) {
        const int rl = rl0 + 8 * half;
        const int tg = it * 64 + rl;
        const float l = lrow[half];
        float wm[16], sumw = 0.f;
#pragma unroll
        for (int m = 0; m < 16; ++m) { wm[m] = s.wsum[rl][m]; sumw += wm[m]; }
        const float w0 = l - sumw;
        const float inv = 1.f / l;
#pragma unroll
        for (int nt = 0; nt < 8; ++nt) {
            const int d0 = nt * 8 + 2 * kq;
            float acc0 = o[nt][half * 2 + 0] + w0 * s.pev[0][d0];
            float acc1 = o[nt][half * 2 + 1] + w0 * s.pev[0][d0 + 1];
#pragma unroll
            for (int m = 1; m <= 16; ++m) {
                acc0 = fmaf(wm[m - 1], s.pev[m][d0], acc0);
                acc1 = fmaf(wm[m - 1], s.pev[m][d0 + 1], acc1);
            }
            float2 ov = make_float2(acc0 * inv, acc1 * inv);
            *(float2*)&g_att[((size_t)(bidx * Tt) + tg) * Uu + h * DH + d0] = ov;
        }
    }
}

// ---------------------------------------------------------------------------
// LayerNorm over last dim (512), eps = 1e-3.  Reads g_proj device global.
// ---------------------------------------------------------------------------
__global__ __launch_bounds__(128) void ln_kernel(
    const float* __restrict__ gamma,
    const float* __restrict__ beta, float* __restrict__ out)
{
    const int row = blockIdx.x;
    const int tid = threadIdx.x;
    float4 v = *(const float4*)&g_proj[(size_t)row * Uu + tid * 4];
    float sum = v.x + v.y + v.z + v.w;
    float sq = v.x * v.x + v.y * v.y + v.z * v.z + v.w * v.w;
#pragma unroll
    for (int off = 16; off; off >>= 1) {
        sum += __shfl_xor_sync(0xffffffffu, sum, off);
        sq  += __shfl_xor_sync(0xffffffffu, sq, off);
    }
    __shared__ float red[8];
    int warp = tid >> 5, lane = tid & 31;
    if (lane == 0) { red[warp] = sum; red[4 + warp] = sq; }
    __syncthreads();
    sum = red[0] + red[1] + red[2] + red[3];
    sq  = red[4] + red[5] + red[6] + red[7];
    float mu = sum * (1.f / Uu);
    float var = sq * (1.f / Uu) - mu * mu;
    float rstd = rsqrtf(var + 1e-3f);
    float4 g = *(const float4*)&gamma[tid * 4];
    float4 be = *(const float4*)&beta[tid * 4];
    float4 o;
    o.x = (v.x - mu) * rstd * g.x + be.x;
    o.y = (v.y - mu) * rstd * g.y + be.y;
    o.z = (v.z - mu) * rstd * g.z + be.z;
    o.w = (v.w - mu) * rstd * g.w + be.w;
    *(float4*)&out[(size_t)row * Uu + tid * 4] = o;
}

// ---------------------------------------------------------------------------
// Input binding: detect permutation from in_sizes (sizes distinguish order).
// ---------------------------------------------------------------------------
extern "C" void kernel_launch(void* const* d_in, const int* in_sizes, int n_in,
                              void* d_out, int out_size) {
    (void)n_in; (void)out_size;

    int iq, ik, iv, iWq, ibq, iWk, ibk, iWv, ibv, iWo, ibo, ig, ibe, ipk, ipv;
    if (in_sizes[0] == Bb * Tt * Uu) {
        // insertion order
        iq = 0; ik = 1; iv = 2; iWq = 3; ibq = 4; iWk = 5; ibk = 6;
        iWv = 7; ibv = 8; iWo = 9; ibo = 10; ig = 11; ibe = 12; ipk = 13; ipv = 14;
    } else if (in_sizes[0] == Uu * Uu) {
        // ASCII sort (uppercase first)
        iWk = 0; iWo = 1; iWq = 2; iWv = 3; ibe = 4; ibk = 5; ibo = 6;
        ibq = 7; ibv = 8; ig = 9; ik = 10; ipk = 11; ipv = 12; iq = 13; iv = 14;
    } else {
        // case-insensitive sort
        ibe = 0; ibk = 1; ibo = 2; ibq = 3; ibv = 4; ig = 5; ik = 6;
        ipk = 7; ipv = 8; iq = 9; iv = 10; iWk = 11; iWo = 12; iWq = 13; iWv = 14;
    }

    const float* q    = (const float*)d_in[iq];
    const float* k    = (const float*)d_in[ik];
    const float* v    = (const float*)d_in[iv];
    const float* Wq   = (const float*)d_in[iWq];
    const float* bq   = (const float*)d_in[ibq];
    const float* Wk   = (const float*)d_in[iWk];
    const float* bk   = (const float*)d_in[ibk];
    const float* Wv   = (const float*)d_in[iWv];
    const float* bv   = (const float*)d_in[ibv];
    const float* Wo   = (const float*)d_in[iWo];
    const float* bo   = (const float*)d_in[ibo];
    const float* gamma= (const float*)d_in[ig];
    const float* beta = (const float*)d_in[ibe];
    const float* pek  = (const float*)d_in[ipk];
    const float* pev  = (const float*)d_in[ipv];
    float* out = (float*)d_out;

    cudaFuncSetAttribute(attn_kernel, cudaFuncAttributeMaxDynamicSharedMemorySize,
                         (int)sizeof(AttnSmem));
    cudaFuncSetAttribute(gemm_tf32<0>, cudaFuncAttributeMaxDynamicSharedMemorySize,
                         (int)sizeof(GemmSmem));
    cudaFuncSetAttribute(gemm_tf32<1>, cudaFuncAttributeMaxDynamicSharedMemorySize,
                         (int)sizeof(GemmSmem));

    float* g_att_p; cudaGetSymbolAddress((void**)&g_att_p, g_att);

    // Q/K/V projections merged into one launch (z = 0/1/2)
    gemm_tf32<0><<<dim3(4, 64, 3), 256, sizeof(GemmSmem)>>>(
        q, k, v, Wq, Wk, Wv, bq, bk, bv, nullptr);

    attn_kernel<<<dim3(16, 64), 128, sizeof(AttnSmem)>>>(pek, pev);

    // Output projection + relu + residual (A = g_att via first slot, W = Wo, bias = bo)
    gemm_tf32<1><<<dim3(4, 64, 1), 256, sizeof(GemmSmem)>>>(
        g_att_p, nullptr, nullptr, Wo, nullptr, nullptr, bo, nullptr, nullptr, q);

    ln_kernel<<<MR, 128>>>(gamma, beta, out);
}